// round 1
// baseline (speedup 1.0000x reference)
#include <cuda_runtime.h>
#include <cuda_bf16.h>

// ---------------- problem constants ----------------
#define BS   16
#define ALEN 1024
#define PLEN 2048
#define LDIM 768

// ---------------- scratch (device globals; no cudaMalloc allowed) ----------
__device__ float g_Ag[(size_t)BS * ALEN * LDIM];   // 16*1024*768
__device__ float g_W [(size_t)BS * PLEN * ALEN];   // 16*2048*1024
__device__ float g_MP[(size_t)BS * PLEN * LDIM];   // 16*2048*768
__device__ float g_MA[(size_t)BS * ALEN * LDIM];   // 16*1024*768

// ---------------- tiled SGEMM ----------------
// C[M,N] = op_A(A) * op_B(B) (+bias)(+relu), batched via blockIdx.z
// AMODE: 0 = A row-major [M,K] (lda = row stride)
//        1 = A is stored transposed: A'[K,M] row-major (lda = row stride of A')
//        2 = A generated on the fly: k <  K/2 : A1[m,k]      - A2[m,k]
//                                    k >= K/2 : A1[m,k-K/2]  * A2[m,k-K/2]
//            (A1/A2 row stride = lda = K/2)
// BMODE: 0 = B row-major [K,N] (ldb = row stride)
//        1 = B stored transposed: B'[N,K] row-major (ldb = row stride of B')
// EPI:   0 = none, 1 = +bias, 2 = relu(+bias)
#define BM 128
#define BN 128
#define BK 8

template<int AMODE, int BMODE, int EPI>
__global__ __launch_bounds__(256)
void gemm_k(const float* __restrict__ Aptr, const float* __restrict__ A2ptr,
            const float* __restrict__ Bptr, const float* __restrict__ biasPtr,
            float* __restrict__ Cptr,
            int M, int N, int K,
            int lda, int ldb, int ldc,
            long long bsA, long long bsB, long long bsC)
{
    __shared__ float As[BK][BM];
    __shared__ float Bs[BK][BN];

    const int tid = threadIdx.x;
    const long long bz = blockIdx.z;
    const float* A  = Aptr  + bsA * bz;
    const float* A2 = A2ptr;                 // only used when AMODE==2 (grid.z==1)
    const float* B  = Bptr  + bsB * bz;
    float*       C  = Cptr  + bsC * bz;

    const int bm = blockIdx.y * BM;
    const int bn = blockIdx.x * BN;

    const int tx = tid & 15;   // n-direction (16)
    const int ty = tid >> 4;   // m-direction (16)

    float acc[8][8];
#pragma unroll
    for (int i = 0; i < 8; i++)
#pragma unroll
        for (int j = 0; j < 8; j++) acc[i][j] = 0.f;

    for (int k0 = 0; k0 < K; k0 += BK) {
        // ---- load A tile into As[k][m] ----
        if (AMODE == 0 || AMODE == 2) {
            const int r  = tid >> 1;          // 0..127 : m within tile
            const int c4 = (tid & 1) * 4;     // 0 or 4 : k within tile
            float4 v;
            if (AMODE == 0) {
                v = *reinterpret_cast<const float4*>(
                        A + (long long)(bm + r) * lda + (k0 + c4));
            } else {
                const int half = K >> 1;
                const int kcol = (k0 < half) ? (k0 + c4) : (k0 + c4 - half);
                const float4 m4 = *reinterpret_cast<const float4*>(
                        A  + (long long)(bm + r) * lda + kcol);
                const float4 g4 = *reinterpret_cast<const float4*>(
                        A2 + (long long)(bm + r) * lda + kcol);
                if (k0 < half) {
                    v.x = m4.x - g4.x; v.y = m4.y - g4.y;
                    v.z = m4.z - g4.z; v.w = m4.w - g4.w;
                } else {
                    v.x = m4.x * g4.x; v.y = m4.y * g4.y;
                    v.z = m4.z * g4.z; v.w = m4.w * g4.w;
                }
            }
            As[c4 + 0][r] = v.x; As[c4 + 1][r] = v.y;
            As[c4 + 2][r] = v.z; As[c4 + 3][r] = v.w;
        } else { // AMODE==1 : A'[K,M], tile rows are k
            const int r = tid >> 5;           // k 0..7
            const int c = (tid & 31) * 4;     // m
            float4 v = *reinterpret_cast<const float4*>(
                    A + (long long)(k0 + r) * lda + (bm + c));
            *reinterpret_cast<float4*>(&As[r][c]) = v;
        }

        // ---- load B tile into Bs[k][n] ----
        if (BMODE == 0) {
            const int r = tid >> 5;           // k 0..7
            const int c = (tid & 31) * 4;     // n
            float4 v = *reinterpret_cast<const float4*>(
                    B + (long long)(k0 + r) * ldb + (bn + c));
            *reinterpret_cast<float4*>(&Bs[r][c]) = v;
        } else { // B'[N,K]
            const int n  = tid >> 1;          // 0..127
            const int c4 = (tid & 1) * 4;     // k
            float4 v = *reinterpret_cast<const float4*>(
                    B + (long long)(bn + n) * ldb + (k0 + c4));
            Bs[c4 + 0][n] = v.x; Bs[c4 + 1][n] = v.y;
            Bs[c4 + 2][n] = v.z; Bs[c4 + 3][n] = v.w;
        }

        __syncthreads();

#pragma unroll
        for (int kk = 0; kk < BK; kk++) {
            float a[8], b[8];
            *reinterpret_cast<float4*>(a)     = *reinterpret_cast<const float4*>(&As[kk][ty * 4]);
            *reinterpret_cast<float4*>(a + 4) = *reinterpret_cast<const float4*>(&As[kk][64 + ty * 4]);
            *reinterpret_cast<float4*>(b)     = *reinterpret_cast<const float4*>(&Bs[kk][tx * 4]);
            *reinterpret_cast<float4*>(b + 4) = *reinterpret_cast<const float4*>(&Bs[kk][64 + tx * 4]);
#pragma unroll
            for (int i = 0; i < 8; i++)
#pragma unroll
                for (int j = 0; j < 8; j++)
                    acc[i][j] = fmaf(a[i], b[j], acc[i][j]);
        }
        __syncthreads();
    }

    // ---- epilogue + store ----
#pragma unroll
    for (int i = 0; i < 8; i++) {
        const int mrow = bm + ((i < 4) ? (ty * 4 + i) : (64 + ty * 4 + (i - 4)));
#pragma unroll
        for (int jh = 0; jh < 2; jh++) {
            const int ncol = bn + jh * 64 + tx * 4;
            float4 v;
            v.x = acc[i][jh * 4 + 0];
            v.y = acc[i][jh * 4 + 1];
            v.z = acc[i][jh * 4 + 2];
            v.w = acc[i][jh * 4 + 3];
            if (EPI >= 1) {
                const float4 bsv = *reinterpret_cast<const float4*>(biasPtr + ncol);
                v.x += bsv.x; v.y += bsv.y; v.z += bsv.z; v.w += bsv.w;
            }
            if (EPI == 2) {
                v.x = fmaxf(v.x, 0.f); v.y = fmaxf(v.y, 0.f);
                v.z = fmaxf(v.z, 0.f); v.w = fmaxf(v.w, 0.f);
            }
            *reinterpret_cast<float4*>(C + (long long)mrow * ldc + ncol) = v;
        }
    }
}

// ---------------- row softmax over 1024 columns --------------------------
__global__ __launch_bounds__(256)
void softmax1024(float* __restrict__ W)
{
    const long long row = blockIdx.x;
    float* w = W + row * 1024;
    const int t = threadIdx.x;          // 256 threads * float4 = 1024

    float4 v = reinterpret_cast<float4*>(w)[t];

    float m = fmaxf(fmaxf(v.x, v.y), fmaxf(v.z, v.w));
#pragma unroll
    for (int o = 16; o > 0; o >>= 1) m = fmaxf(m, __shfl_xor_sync(0xffffffffu, m, o));

    __shared__ float smax[8];
    __shared__ float ssum[8];
    if ((t & 31) == 0) smax[t >> 5] = m;
    __syncthreads();
    float bmax = smax[0];
#pragma unroll
    for (int i = 1; i < 8; i++) bmax = fmaxf(bmax, smax[i]);

    v.x = __expf(v.x - bmax);
    v.y = __expf(v.y - bmax);
    v.z = __expf(v.z - bmax);
    v.w = __expf(v.w - bmax);

    float s = v.x + v.y + v.z + v.w;
#pragma unroll
    for (int o = 16; o > 0; o >>= 1) s += __shfl_xor_sync(0xffffffffu, s, o);
    if ((t & 31) == 0) ssum[t >> 5] = s;
    __syncthreads();
    float tot = 0.f;
#pragma unroll
    for (int i = 0; i < 8; i++) tot += ssum[i];

    const float inv = 1.f / tot;
    v.x *= inv; v.y *= inv; v.z *= inv; v.w *= inv;
    reinterpret_cast<float4*>(w)[t] = v;
}

// ---------------- launch ----------------
extern "C" void kernel_launch(void* const* d_in, const int* in_sizes, int n_in,
                              void* d_out, int out_size)
{
    (void)in_sizes; (void)n_in; (void)out_size;
    const float* A     = (const float*)d_in[0];
    const float* P     = (const float*)d_in[1];
    const float* G_w   = (const float*)d_in[2];
    const float* G_b   = (const float*)d_in[3];
    const float* fca_w = (const float*)d_in[4];
    const float* fca_b = (const float*)d_in[5];
    const float* fcp_w = (const float*)d_in[6];
    const float* fcp_b = (const float*)d_in[7];
    float* out = (float*)d_out;

    float *Ag, *W, *MP, *MA;
    cudaGetSymbolAddress((void**)&Ag, g_Ag);
    cudaGetSymbolAddress((void**)&W,  g_W);
    cudaGetSymbolAddress((void**)&MP, g_MP);
    cudaGetSymbolAddress((void**)&MA, g_MA);

    const dim3 blk(256);

    // 1) Ag = A @ G_w + G_b          [16384,768] = [16384,768]x[768,768]
    gemm_k<0,0,1><<<dim3(LDIM/BN, (BS*ALEN)/BM, 1), blk>>>(
        A, nullptr, G_w, G_b, Ag,
        BS*ALEN, LDIM, LDIM, LDIM, LDIM, LDIM, 0, 0, 0);

    // 2) W_b = P_b @ Ag_b^T          per batch [2048,1024] = [2048,768]x[768,1024]
    gemm_k<0,1,0><<<dim3(ALEN/BN, PLEN/BM, BS), blk>>>(
        P, nullptr, Ag, nullptr, W,
        PLEN, ALEN, LDIM, LDIM, LDIM, ALEN,
        (long long)PLEN*LDIM, (long long)ALEN*LDIM, (long long)PLEN*ALEN);

    // 3) softmax over a-dim (row length 1024)
    softmax1024<<<BS*PLEN, 256>>>(W);

    // 4) MP_b = W_b @ Ag_b           [2048,768] = [2048,1024]x[1024,768]
    gemm_k<0,0,0><<<dim3(LDIM/BN, PLEN/BM, BS), blk>>>(
        W, nullptr, Ag, nullptr, MP,
        PLEN, LDIM, ALEN, ALEN, LDIM, LDIM,
        (long long)PLEN*ALEN, (long long)ALEN*LDIM, (long long)PLEN*LDIM);

    // 5) MA_b = W_b^T @ P_b          [1024,768] = [1024,2048]x[2048,768]   (TN)
    gemm_k<1,0,0><<<dim3(LDIM/BN, ALEN/BM, BS), blk>>>(
        W, nullptr, P, nullptr, MA,
        ALEN, LDIM, PLEN, ALEN, LDIM, LDIM,
        (long long)PLEN*ALEN, (long long)PLEN*LDIM, (long long)ALEN*LDIM);

    // 6) SA = relu(concat(MA-Ag, MA*Ag) @ fca_w + fca_b)   [16384,768], K=1536
    gemm_k<2,0,2><<<dim3(LDIM/BN, (BS*ALEN)/BM, 1), blk>>>(
        MA, Ag, fca_w, fca_b, out,
        BS*ALEN, LDIM, 2*LDIM, LDIM, LDIM, LDIM, 0, 0, 0);

    // 7) SP = relu(concat(MP-P, MP*P) @ fcp_w + fcp_b)     [32768,768], K=1536
    gemm_k<2,0,2><<<dim3(LDIM/BN, (BS*PLEN)/BM, 1), blk>>>(
        MP, P, fcp_w, fcp_b, out + (long long)BS*ALEN*LDIM,
        BS*PLEN, LDIM, 2*LDIM, LDIM, LDIM, LDIM, 0, 0, 0);
}

// round 3
// speedup vs baseline: 2.2841x; 2.2841x over previous
#include <cuda_runtime.h>
#include <cuda_bf16.h>
#include <cstdint>

// ---------------- problem constants ----------------
#define BSZ   16
#define ALEN 1024
#define PLEN 2048
#define LDIM 768

// ================= scratch (device globals) =================
__device__ __align__(256) float g_Ag[(size_t)BSZ * ALEN * LDIM];
__device__ __align__(256) float g_W [(size_t)BSZ * PLEN * ALEN];
__device__ __align__(256) float g_MP[(size_t)BSZ * PLEN * LDIM];
__device__ __align__(256) float g_MA[(size_t)BSZ * ALEN * LDIM];

// bf16 triple-K operand buffers
__device__ __align__(256) __nv_bfloat16 g_A3  [(size_t)16384 * 2304];
__device__ __align__(256) __nv_bfloat16 g_P3  [(size_t)32768 * 2304];
__device__ __align__(256) __nv_bfloat16 g_Ag3 [(size_t)16384 * 2304];
__device__ __align__(256) __nv_bfloat16 g_AgT3[(size_t)16 * 768 * 3072];
__device__ __align__(256) __nv_bfloat16 g_PT3 [(size_t)16 * 768 * 6144];
__device__ __align__(256) __nv_bfloat16 g_W3  [(size_t)32768 * 3072];
__device__ __align__(256) __nv_bfloat16 g_WT3 [(size_t)16 * 1024 * 6144];
__device__ __align__(256) __nv_bfloat16 g_Gt3 [(size_t)768 * 2304];
__device__ __align__(256) __nv_bfloat16 g_FaT3[(size_t)768 * 4608];
__device__ __align__(256) __nv_bfloat16 g_FpT3[(size_t)768 * 4608];
__device__ __align__(256) __nv_bfloat16 g_U6  [(size_t)16384 * 4608];
__device__ __align__(256) __nv_bfloat16 g_U7  [(size_t)32768 * 4608];

// ================= helpers =================
__device__ __forceinline__ uint32_t smem_u32(const void* p) {
    uint32_t a;
    asm("{ .reg .u64 t; cvta.to.shared.u64 t, %1; cvt.u32.u64 %0, t; }" : "=r"(a) : "l"(p));
    return a;
}

#define LDSM4(r0, r1, r2, r3, a)                                              \
    asm volatile("ldmatrix.sync.aligned.m8n8.x4.shared.b16 {%0,%1,%2,%3}, [%4];" \
                 : "=r"(r0), "=r"(r1), "=r"(r2), "=r"(r3) : "r"(a))

#define MMA16816(c, a0, a1, a2, a3, b0, b1)                                   \
    asm volatile("mma.sync.aligned.m16n8k16.row.col.f32.bf16.bf16.f32 "       \
                 "{%0,%1,%2,%3}, {%4,%5,%6,%7}, {%8,%9}, {%0,%1,%2,%3};"      \
                 : "+f"((c)[0]), "+f"((c)[1]), "+f"((c)[2]), "+f"((c)[3])     \
                 : "r"(a0), "r"(a1), "r"(a2), "r"(a3), "r"(b0), "r"(b1))

// ================= tensor-core GEMM (mma.sync bf16) =================
// C[M,N](f32) = A[M,Kp](bf16 row-major) * B[N,Kp](bf16 row-major)^T
// block tile 128x128, K-chunk 32, 3-stage cp.async pipeline.
// smem tile: 128 rows x 32 bf16, row stride 40 elements (80B) -> conflict-free
// EPI: 0 none, 1 +bias, 2 relu(+bias)
#define TSTRIDE 80                  // bytes per smem row
#define TILEB   (128 * TSTRIDE)     // 10240 B per operand tile
#define STAGEB  (2 * TILEB)         // 20480 B per stage
#define NSTAGE  3
#define SMEMSZ  (NSTAGE * STAGEB)   // 61440 B

__device__ __forceinline__ void ld_tile(uint32_t sdst, const char* g, int rowB, int tid) {
#pragma unroll
    for (int i = 0; i < 2; i++) {
        int idx = i * 256 + tid;          // 512 chunks of 16B
        int row = idx >> 2;
        int c = idx & 3;
        uint32_t so = sdst + row * TSTRIDE + c * 16;
        asm volatile("cp.async.cg.shared.global [%0], [%1], 16;\n"
                     :: "r"(so), "l"(g + (long long)row * rowB + c * 16));
    }
}

template<int EPI>
__global__ __launch_bounds__(256)
void tgemm(const __nv_bfloat16* __restrict__ Aop,
           const __nv_bfloat16* __restrict__ Bop,
           const float* __restrict__ bias,
           float* __restrict__ Cout,
           int N, int Kp,
           long long bsA, long long bsB, long long bsC)
{
    extern __shared__ __align__(128) char smem[];
    const uint32_t sbase = smem_u32(smem);
    const int tid  = threadIdx.x;
    const int wid  = tid >> 5;
    const int lane = tid & 31;
    const int wm = wid & 1;     // 2 warps in m
    const int wn = wid >> 1;    // 4 warps in n

    const int rowB = Kp * 2;
    const char* Abase = ((const char*)Aop) + 2LL * (bsA * blockIdx.z + (long long)blockIdx.y * 128 * Kp);
    const char* Bbase = ((const char*)Bop) + 2LL * (bsB * blockIdx.z + (long long)blockIdx.x * 128 * Kp);

    const int ntiles = Kp >> 5;   // K-chunks of 32

    float c[4][4][4];
#pragma unroll
    for (int i = 0; i < 4; i++)
#pragma unroll
        for (int j = 0; j < 4; j++) {
            c[i][j][0] = 0.f; c[i][j][1] = 0.f; c[i][j][2] = 0.f; c[i][j][3] = 0.f;
        }

    // prologue: 2 stages in flight
#pragma unroll
    for (int s = 0; s < 2; s++) {
        ld_tile(sbase + s * STAGEB,         Abase + s * 64, rowB, tid);
        ld_tile(sbase + s * STAGEB + TILEB, Bbase + s * 64, rowB, tid);
        asm volatile("cp.async.commit_group;\n" ::: "memory");
    }

    // precomputed intra-warp ldmatrix offsets
    const uint32_t aoff = (uint32_t)((wm * 64 + (lane & 15)) * TSTRIDE + ((lane >> 4) << 4));
    const uint32_t boff = (uint32_t)((wn * 32 + ((lane >> 4) << 3) + (lane & 7)) * TSTRIDE
                                     + (((lane >> 3) & 1) << 4));

    for (int ks = 0; ks < ntiles; ks++) {
        const int b = ks % NSTAGE;
        asm volatile("cp.async.wait_group 1;\n" ::: "memory");
        __syncthreads();

        const uint32_t sA = sbase + b * STAGEB;
        const uint32_t sB = sA + TILEB;

#pragma unroll
        for (int kk = 0; kk < 2; kk++) {          // two k16 steps per chunk
            uint32_t bf[8];
            uint32_t ba = sB + boff + kk * 32;
            LDSM4(bf[0], bf[1], bf[2], bf[3], ba);
            LDSM4(bf[4], bf[5], bf[6], bf[7], ba + 16 * TSTRIDE);
#pragma unroll
            for (int mt = 0; mt < 4; mt++) {
                uint32_t a0, a1, a2, a3;
                LDSM4(a0, a1, a2, a3, sA + aoff + mt * 16 * TSTRIDE + kk * 32);
                MMA16816(c[mt][0], a0, a1, a2, a3, bf[0], bf[1]);
                MMA16816(c[mt][1], a0, a1, a2, a3, bf[2], bf[3]);
                MMA16816(c[mt][2], a0, a1, a2, a3, bf[4], bf[5]);
                MMA16816(c[mt][3], a0, a1, a2, a3, bf[6], bf[7]);
            }
        }

        // issue loads for stage ks+2 (buffer (ks+2)%3 is not in use)
        const int kl = ks + 2;
        if (kl < ntiles) {
            const int bl = kl % NSTAGE;
            ld_tile(sbase + bl * STAGEB,         Abase + kl * 64, rowB, tid);
            ld_tile(sbase + bl * STAGEB + TILEB, Bbase + kl * 64, rowB, tid);
        }
        asm volatile("cp.async.commit_group;\n" ::: "memory");
    }

    // ---- epilogue ----
    float* Cb = Cout + bsC * blockIdx.z;
    const int row0 = blockIdx.y * 128 + wm * 64 + (lane >> 2);
    const int col0 = blockIdx.x * 128 + wn * 32 + (lane & 3) * 2;
#pragma unroll
    for (int mt = 0; mt < 4; mt++) {
#pragma unroll
        for (int nt = 0; nt < 4; nt++) {
            const int r = row0 + mt * 16;
            const int cl = col0 + nt * 8;
            float2 v0 = make_float2(c[mt][nt][0], c[mt][nt][1]);
            float2 v1 = make_float2(c[mt][nt][2], c[mt][nt][3]);
            if (EPI >= 1) {
                float2 bv = *reinterpret_cast<const float2*>(bias + cl);
                v0.x += bv.x; v0.y += bv.y; v1.x += bv.x; v1.y += bv.y;
            }
            if (EPI == 2) {
                v0.x = fmaxf(v0.x, 0.f); v0.y = fmaxf(v0.y, 0.f);
                v1.x = fmaxf(v1.x, 0.f); v1.y = fmaxf(v1.y, 0.f);
            }
            *reinterpret_cast<float2*>(Cb + (long long)r * N + cl)       = v0;
            *reinterpret_cast<float2*>(Cb + (long long)(r + 8) * N + cl) = v1;
        }
    }
}

// ================= conversion kernels =================
__device__ __forceinline__ void hilo2(float2 v, __nv_bfloat162& h2, __nv_bfloat162& l2) {
    h2 = __float22bfloat162_rn(v);
    float2 r;
    r.x = v.x - __bfloat162float(h2.x);
    r.y = v.y - __bfloat162float(h2.y);
    l2 = __float22bfloat162_rn(r);
}

// in [R,K] f32 -> out [R,3K] bf16.  bside=0: (hi,hi,lo)  bside=1: (hi,lo,hi)
__global__ void split3_k(const float* __restrict__ in, __nv_bfloat16* __restrict__ out,
                         int K, int bside, long long total2)
{
    long long i = (long long)blockIdx.x * blockDim.x + threadIdx.x;
    if (i >= total2) return;
    long long e = i * 2;
    long long r = e / K;
    int c = (int)(e - r * K);
    float2 v = *reinterpret_cast<const float2*>(in + e);
    __nv_bfloat162 h2, l2;
    hilo2(v, h2, l2);
    __nv_bfloat16* o = out + r * (3LL * K);
    *reinterpret_cast<__nv_bfloat162*>(o + c) = h2;
    *reinterpret_cast<__nv_bfloat162*>(o + c + K)     = bside ? l2 : h2;
    *reinterpret_cast<__nv_bfloat162*>(o + c + 2 * K) = bside ? h2 : l2;
}

// in [R,C] f32 -> out [C,3R] bf16 transposed; batched
__global__ void split3T_k(const float* __restrict__ in, __nv_bfloat16* __restrict__ out,
                          int R, int C, long long inBS, long long outBS, int bside)
{
    __shared__ float t[32][33];
    const float* ib = in + inBS * blockIdx.z;
    __nv_bfloat16* ob = out + outBS * blockIdx.z;
    const int c0 = blockIdx.x * 32, r0 = blockIdx.y * 32;
    const int tx = threadIdx.x, ty = threadIdx.y;
#pragma unroll
    for (int i = 0; i < 4; i++)
        t[ty + i * 8][tx] = ib[(long long)(r0 + ty + i * 8) * C + c0 + tx];
    __syncthreads();
#pragma unroll
    for (int i = 0; i < 4; i++) {
        int c = c0 + ty + i * 8;
        int r = r0 + tx;
        float x = t[tx][ty + i * 8];
        __nv_bfloat16 h = __float2bfloat16(x);
        __nv_bfloat16 l = __float2bfloat16(x - __bfloat162float(h));
        __nv_bfloat16* o = ob + (long long)c * (3LL * R);
        o[r] = h;
        o[r + R]     = bside ? l : h;
        o[r + 2 * R] = bside ? h : l;
    }
}

// U = concat(X - Y, X * Y) over L=768; out [R, 3*1536] bf16 (A-side pattern)
__global__ void combo3_k(const float* __restrict__ X, const float* __restrict__ Y,
                         __nv_bfloat16* __restrict__ out, long long total2)
{
    long long i = (long long)blockIdx.x * blockDim.x + threadIdx.x;
    if (i >= total2) return;
    long long e = i * 2;
    long long r = e / 1536;
    int c = (int)(e - r * 1536);
    float2 x, y, u;
    if (c < 768) {
        x = *reinterpret_cast<const float2*>(X + r * 768 + c);
        y = *reinterpret_cast<const float2*>(Y + r * 768 + c);
        u.x = x.x - y.x; u.y = x.y - y.y;
    } else {
        int j = c - 768;
        x = *reinterpret_cast<const float2*>(X + r * 768 + j);
        y = *reinterpret_cast<const float2*>(Y + r * 768 + j);
        u.x = x.x * y.x; u.y = x.y * y.y;
    }
    __nv_bfloat162 h2, l2;
    hilo2(u, h2, l2);
    __nv_bfloat16* o = out + r * 4608;
    *reinterpret_cast<__nv_bfloat162*>(o + c)        = h2;
    *reinterpret_cast<__nv_bfloat162*>(o + c + 1536) = h2;
    *reinterpret_cast<__nv_bfloat162*>(o + c + 3072) = l2;
}

// ================= softmax over 1024 columns =================
__global__ __launch_bounds__(256)
void softmax1024(float* __restrict__ W)
{
    const long long row = blockIdx.x;
    float* w = W + row * 1024;
    const int t = threadIdx.x;
    float4 v = reinterpret_cast<float4*>(w)[t];
    float m = fmaxf(fmaxf(v.x, v.y), fmaxf(v.z, v.w));
#pragma unroll
    for (int o = 16; o > 0; o >>= 1) m = fmaxf(m, __shfl_xor_sync(0xffffffffu, m, o));
    __shared__ float smax[8], ssum[8];
    if ((t & 31) == 0) smax[t >> 5] = m;
    __syncthreads();
    float bmax = smax[0];
#pragma unroll
    for (int i = 1; i < 8; i++) bmax = fmaxf(bmax, smax[i]);
    v.x = __expf(v.x - bmax); v.y = __expf(v.y - bmax);
    v.z = __expf(v.z - bmax); v.w = __expf(v.w - bmax);
    float s = v.x + v.y + v.z + v.w;
#pragma unroll
    for (int o = 16; o > 0; o >>= 1) s += __shfl_xor_sync(0xffffffffu, s, o);
    if ((t & 31) == 0) ssum[t >> 5] = s;
    __syncthreads();
    float tot = 0.f;
#pragma unroll
    for (int i = 0; i < 8; i++) tot += ssum[i];
    const float inv = 1.f / tot;
    v.x *= inv; v.y *= inv; v.z *= inv; v.w *= inv;
    reinterpret_cast<float4*>(w)[t] = v;
}

// ================= launch =================
static inline int blk2(long long total2) { return (int)((total2 + 255) / 256); }

extern "C" void kernel_launch(void* const* d_in, const int* in_sizes, int n_in,
                              void* d_out, int out_size)
{
    (void)in_sizes; (void)n_in; (void)out_size;
    const float* A     = (const float*)d_in[0];
    const float* P     = (const float*)d_in[1];
    const float* G_w   = (const float*)d_in[2];
    const float* G_b   = (const float*)d_in[3];
    const float* fca_w = (const float*)d_in[4];
    const float* fca_b = (const float*)d_in[5];
    const float* fcp_w = (const float*)d_in[6];
    const float* fcp_b = (const float*)d_in[7];
    float* out = (float*)d_out;

    float *Ag, *W, *MP, *MA;
    cudaGetSymbolAddress((void**)&Ag, g_Ag);
    cudaGetSymbolAddress((void**)&W,  g_W);
    cudaGetSymbolAddress((void**)&MP, g_MP);
    cudaGetSymbolAddress((void**)&MA, g_MA);
    __nv_bfloat16 *A3, *P3, *Ag3, *AgT3, *PT3, *W3, *WT3, *Gt3, *FaT3, *FpT3, *U6, *U7;
    cudaGetSymbolAddress((void**)&A3,   g_A3);
    cudaGetSymbolAddress((void**)&P3,   g_P3);
    cudaGetSymbolAddress((void**)&Ag3,  g_Ag3);
    cudaGetSymbolAddress((void**)&AgT3, g_AgT3);
    cudaGetSymbolAddress((void**)&PT3,  g_PT3);
    cudaGetSymbolAddress((void**)&W3,   g_W3);
    cudaGetSymbolAddress((void**)&WT3,  g_WT3);
    cudaGetSymbolAddress((void**)&Gt3,  g_Gt3);
    cudaGetSymbolAddress((void**)&FaT3, g_FaT3);
    cudaGetSymbolAddress((void**)&FpT3, g_FpT3);
    cudaGetSymbolAddress((void**)&U6,   g_U6);
    cudaGetSymbolAddress((void**)&U7,   g_U7);

    cudaFuncSetAttribute(tgemm<0>, cudaFuncAttributeMaxDynamicSharedMemorySize, SMEMSZ);
    cudaFuncSetAttribute(tgemm<1>, cudaFuncAttributeMaxDynamicSharedMemorySize, SMEMSZ);
    cudaFuncSetAttribute(tgemm<2>, cudaFuncAttributeMaxDynamicSharedMemorySize, SMEMSZ);

    const dim3 tb(32, 8);

    // --- input conversions ---
    split3_k<<<blk2(16384LL*768/2), 256>>>(A, A3, 768, 0, 16384LL*768/2);          // A (A-side)
    split3_k<<<blk2(32768LL*768/2), 256>>>(P, P3, 768, 0, 32768LL*768/2);          // P (A-side)
    split3T_k<<<dim3(24, 24, 1),  tb>>>(G_w,   Gt3,  768, 768, 0, 0, 1);           // G_w^T (B-side)
    split3T_k<<<dim3(24, 48, 1),  tb>>>(fca_w, FaT3, 1536, 768, 0, 0, 1);          // fca_w^T (B-side)
    split3T_k<<<dim3(24, 48, 1),  tb>>>(fcp_w, FpT3, 1536, 768, 0, 0, 1);          // fcp_w^T (B-side)
    split3T_k<<<dim3(24, 64, 16), tb>>>(P, PT3, 2048, 768,
                                        2048LL*768, 768LL*6144, 1);                // P^T per batch (B-side)

    // 1) Ag = A @ G_w + G_b
    tgemm<1><<<dim3(6, 128, 1), 256, SMEMSZ>>>(A3, Gt3, G_b, Ag, 768, 2304, 0, 0, 0);

    split3_k<<<blk2(16384LL*768/2), 256>>>(Ag, Ag3, 768, 1, 16384LL*768/2);        // Ag rows (B-side)
    split3T_k<<<dim3(24, 32, 16), tb>>>(Ag, AgT3, 1024, 768,
                                        1024LL*768, 768LL*3072, 1);                // Ag^T per batch (B-side)

    // 2) W = P @ Ag^T (per batch)
    tgemm<0><<<dim3(8, 16, 16), 256, SMEMSZ>>>(P3, Ag3, nullptr, W, 1024, 2304,
                                               2048LL*2304, 1024LL*2304, 2048LL*1024);
    // 3) softmax over a-dim
    softmax1024<<<BSZ * PLEN, 256>>>(W);

    split3_k<<<blk2(32768LL*1024/2), 256>>>(W, W3, 1024, 0, 32768LL*1024/2);       // W rows (A-side)
    split3T_k<<<dim3(32, 64, 16), tb>>>(W, WT3, 2048, 1024,
                                        2048LL*1024, 1024LL*6144, 0);              // W^T per batch (A-side)

    // 4) MP = W @ Ag (per batch)
    tgemm<0><<<dim3(6, 16, 16), 256, SMEMSZ>>>(W3, AgT3, nullptr, MP, 768, 3072,
                                               2048LL*3072, 768LL*3072, 2048LL*768);
    // 5) MA = W^T @ P (per batch)
    tgemm<0><<<dim3(6, 8, 16), 256, SMEMSZ>>>(WT3, PT3, nullptr, MA, 768, 6144,
                                              1024LL*6144, 768LL*6144, 1024LL*768);

    // 6) SA = relu(concat(MA-Ag, MA*Ag) @ fca_w + fca_b)
    combo3_k<<<blk2(16384LL*1536/2), 256>>>(MA, Ag, U6, 16384LL*1536/2);
    tgemm<2><<<dim3(6, 128, 1), 256, SMEMSZ>>>(U6, FaT3, fca_b, out, 768, 4608, 0, 0, 0);

    // 7) SP = relu(concat(MP-P, MP*P) @ fcp_w + fcp_b)
    combo3_k<<<blk2(32768LL*1536/2), 256>>>(MP, P, U7, 32768LL*1536/2);
    tgemm<2><<<dim3(6, 256, 1), 256, SMEMSZ>>>(U7, FpT3, fcp_b,
                                               out + 16384LL * 768, 768, 4608, 0, 0, 0);
}

// round 4
// speedup vs baseline: 4.1220x; 1.8047x over previous
#include <cuda_runtime.h>
#include <cuda_bf16.h>
#include <cuda_fp16.h>
#include <cstdint>

// ---------------- problem constants ----------------
#define BSZ   16
#define ALEN 1024
#define PLEN 2048
#define LDIM 768

// ================= scratch (device globals) =================
__device__ __align__(256) float g_Ag[(size_t)BSZ * ALEN * LDIM];
__device__ __align__(256) float g_W [(size_t)BSZ * PLEN * ALEN];
__device__ __align__(256) float g_MP[(size_t)BSZ * PLEN * LDIM];
__device__ __align__(256) float g_MA[(size_t)BSZ * ALEN * LDIM];

// bf16 triple-K operand buffers (logit chain only)
__device__ __align__(256) __nv_bfloat16 g_A3 [(size_t)16384 * 2304];
__device__ __align__(256) __nv_bfloat16 g_P3 [(size_t)32768 * 2304];
__device__ __align__(256) __nv_bfloat16 g_Ag3[(size_t)16384 * 2304];
__device__ __align__(256) __nv_bfloat16 g_Gt3[(size_t)768 * 2304];

// fp16 single operand buffers (post-softmax chain)
__device__ __align__(256) __half g_Wh  [(size_t)32768 * 1024];
__device__ __align__(256) __half g_WTh [(size_t)16 * 1024 * 2048];
__device__ __align__(256) __half g_AgTh[(size_t)16 * 768 * 1024];
__device__ __align__(256) __half g_PTh [(size_t)16 * 768 * 2048];
__device__ __align__(256) __half g_U6h [(size_t)16384 * 1536];
__device__ __align__(256) __half g_U7h [(size_t)32768 * 1536];
__device__ __align__(256) __half g_Fah [(size_t)768 * 1536];
__device__ __align__(256) __half g_Fph [(size_t)768 * 1536];

// ================= helpers =================
__device__ __forceinline__ uint32_t smem_u32(const void* p) {
    uint32_t a;
    asm("{ .reg .u64 t; cvta.to.shared.u64 t, %1; cvt.u32.u64 %0, t; }" : "=r"(a) : "l"(p));
    return a;
}

#define LDSM4(r0, r1, r2, r3, a)                                              \
    asm volatile("ldmatrix.sync.aligned.m8n8.x4.shared.b16 {%0,%1,%2,%3}, [%4];" \
                 : "=r"(r0), "=r"(r1), "=r"(r2), "=r"(r3) : "r"(a))

__device__ __forceinline__ void mma_bf16(float* c, uint32_t a0, uint32_t a1, uint32_t a2,
                                         uint32_t a3, uint32_t b0, uint32_t b1) {
    asm volatile("mma.sync.aligned.m16n8k16.row.col.f32.bf16.bf16.f32 "
                 "{%0,%1,%2,%3}, {%4,%5,%6,%7}, {%8,%9}, {%0,%1,%2,%3};"
                 : "+f"(c[0]), "+f"(c[1]), "+f"(c[2]), "+f"(c[3])
                 : "r"(a0), "r"(a1), "r"(a2), "r"(a3), "r"(b0), "r"(b1));
}
__device__ __forceinline__ void mma_fp16(float* c, uint32_t a0, uint32_t a1, uint32_t a2,
                                         uint32_t a3, uint32_t b0, uint32_t b1) {
    asm volatile("mma.sync.aligned.m16n8k16.row.col.f32.f16.f16.f32 "
                 "{%0,%1,%2,%3}, {%4,%5,%6,%7}, {%8,%9}, {%0,%1,%2,%3};"
                 : "+f"(c[0]), "+f"(c[1]), "+f"(c[2]), "+f"(c[3])
                 : "r"(a0), "r"(a1), "r"(a2), "r"(a3), "r"(b0), "r"(b1));
}

// ================= tensor-core GEMM (mma.sync) =================
// C[M,N](f32) = A[M,Kp](16-bit row-major) * B[N,Kp](16-bit row-major)^T
// block tile 128x128, K-chunk 32, 3-stage cp.async pipeline.
// EPI: 0 none, 1 +bias, 2 relu(+bias).  FP16: element type selector.
#define TSTRIDE 80                  // bytes per smem row
#define TILEB   (128 * TSTRIDE)
#define STAGEB  (2 * TILEB)
#define NSTAGE  3
#define SMEMSZ  (NSTAGE * STAGEB)   // 61440 B

__device__ __forceinline__ void ld_tile(uint32_t sdst, const char* g, int rowB, int tid) {
#pragma unroll
    for (int i = 0; i < 2; i++) {
        int idx = i * 256 + tid;
        int row = idx >> 2;
        int c = idx & 3;
        uint32_t so = sdst + row * TSTRIDE + c * 16;
        asm volatile("cp.async.cg.shared.global [%0], [%1], 16;\n"
                     :: "r"(so), "l"(g + (long long)row * rowB + c * 16));
    }
}

template<int EPI, bool FP16>
__global__ __launch_bounds__(256)
void tgemm(const uint16_t* __restrict__ Aop,
           const uint16_t* __restrict__ Bop,
           const float* __restrict__ bias,
           float* __restrict__ Cout,
           int N, int Kp,
           long long bsA, long long bsB, long long bsC)
{
    extern __shared__ __align__(128) char smem[];
    const uint32_t sbase = smem_u32(smem);
    const int tid  = threadIdx.x;
    const int wid  = tid >> 5;
    const int lane = tid & 31;
    const int wm = wid & 1;
    const int wn = wid >> 1;

    const int rowB = Kp * 2;
    const char* Abase = ((const char*)Aop) + 2LL * (bsA * blockIdx.z + (long long)blockIdx.y * 128 * Kp);
    const char* Bbase = ((const char*)Bop) + 2LL * (bsB * blockIdx.z + (long long)blockIdx.x * 128 * Kp);

    const int ntiles = Kp >> 5;

    float c[4][4][4];
#pragma unroll
    for (int i = 0; i < 4; i++)
#pragma unroll
        for (int j = 0; j < 4; j++) {
            c[i][j][0] = 0.f; c[i][j][1] = 0.f; c[i][j][2] = 0.f; c[i][j][3] = 0.f;
        }

#pragma unroll
    for (int s = 0; s < 2; s++) {
        ld_tile(sbase + s * STAGEB,         Abase + s * 64, rowB, tid);
        ld_tile(sbase + s * STAGEB + TILEB, Bbase + s * 64, rowB, tid);
        asm volatile("cp.async.commit_group;\n" ::: "memory");
    }

    const uint32_t aoff = (uint32_t)((wm * 64 + (lane & 15)) * TSTRIDE + ((lane >> 4) << 4));
    const uint32_t boff = (uint32_t)((wn * 32 + ((lane >> 4) << 3) + (lane & 7)) * TSTRIDE
                                     + (((lane >> 3) & 1) << 4));

    for (int ks = 0; ks < ntiles; ks++) {
        const int b = ks % NSTAGE;
        asm volatile("cp.async.wait_group 1;\n" ::: "memory");
        __syncthreads();

        const uint32_t sA = sbase + b * STAGEB;
        const uint32_t sB = sA + TILEB;

#pragma unroll
        for (int kk = 0; kk < 2; kk++) {
            uint32_t bf[8];
            uint32_t ba = sB + boff + kk * 32;
            LDSM4(bf[0], bf[1], bf[2], bf[3], ba);
            LDSM4(bf[4], bf[5], bf[6], bf[7], ba + 16 * TSTRIDE);
#pragma unroll
            for (int mt = 0; mt < 4; mt++) {
                uint32_t a0, a1, a2, a3;
                LDSM4(a0, a1, a2, a3, sA + aoff + mt * 16 * TSTRIDE + kk * 32);
                if (FP16) {
                    mma_fp16(c[mt][0], a0, a1, a2, a3, bf[0], bf[1]);
                    mma_fp16(c[mt][1], a0, a1, a2, a3, bf[2], bf[3]);
                    mma_fp16(c[mt][2], a0, a1, a2, a3, bf[4], bf[5]);
                    mma_fp16(c[mt][3], a0, a1, a2, a3, bf[6], bf[7]);
                } else {
                    mma_bf16(c[mt][0], a0, a1, a2, a3, bf[0], bf[1]);
                    mma_bf16(c[mt][1], a0, a1, a2, a3, bf[2], bf[3]);
                    mma_bf16(c[mt][2], a0, a1, a2, a3, bf[4], bf[5]);
                    mma_bf16(c[mt][3], a0, a1, a2, a3, bf[6], bf[7]);
                }
            }
        }

        const int kl = ks + 2;
        if (kl < ntiles) {
            const int bl = kl % NSTAGE;
            ld_tile(sbase + bl * STAGEB,         Abase + kl * 64, rowB, tid);
            ld_tile(sbase + bl * STAGEB + TILEB, Bbase + kl * 64, rowB, tid);
        }
        asm volatile("cp.async.commit_group;\n" ::: "memory");
    }

    float* Cb = Cout + bsC * blockIdx.z;
    const int row0 = blockIdx.y * 128 + wm * 64 + (lane >> 2);
    const int col0 = blockIdx.x * 128 + wn * 32 + (lane & 3) * 2;
#pragma unroll
    for (int mt = 0; mt < 4; mt++) {
#pragma unroll
        for (int nt = 0; nt < 4; nt++) {
            const int r = row0 + mt * 16;
            const int cl = col0 + nt * 8;
            float2 v0 = make_float2(c[mt][nt][0], c[mt][nt][1]);
            float2 v1 = make_float2(c[mt][nt][2], c[mt][nt][3]);
            if (EPI >= 1) {
                float2 bv = *reinterpret_cast<const float2*>(bias + cl);
                v0.x += bv.x; v0.y += bv.y; v1.x += bv.x; v1.y += bv.y;
            }
            if (EPI == 2) {
                v0.x = fmaxf(v0.x, 0.f); v0.y = fmaxf(v0.y, 0.f);
                v1.x = fmaxf(v1.x, 0.f); v1.y = fmaxf(v1.y, 0.f);
            }
            *reinterpret_cast<float2*>(Cb + (long long)r * N + cl)       = v0;
            *reinterpret_cast<float2*>(Cb + (long long)(r + 8) * N + cl) = v1;
        }
    }
}

// ================= conversion kernels =================
__device__ __forceinline__ void hilo2(float2 v, __nv_bfloat162& h2, __nv_bfloat162& l2) {
    h2 = __float22bfloat162_rn(v);
    float2 r;
    r.x = v.x - __bfloat162float(h2.x);
    r.y = v.y - __bfloat162float(h2.y);
    l2 = __float22bfloat162_rn(r);
}

// in [R,K] f32 -> out [R,3K] bf16.  bside=0: (hi,hi,lo)  bside=1: (hi,lo,hi)
__global__ void split3_k(const float* __restrict__ in, __nv_bfloat16* __restrict__ out,
                         int K, int bside, long long total2)
{
    long long i = (long long)blockIdx.x * blockDim.x + threadIdx.x;
    if (i >= total2) return;
    long long e = i * 2;
    long long r = e / K;
    int c = (int)(e - r * K);
    float2 v = *reinterpret_cast<const float2*>(in + e);
    __nv_bfloat162 h2, l2;
    hilo2(v, h2, l2);
    __nv_bfloat16* o = out + r * (3LL * K);
    *reinterpret_cast<__nv_bfloat162*>(o + c) = h2;
    *reinterpret_cast<__nv_bfloat162*>(o + c + K)     = bside ? l2 : h2;
    *reinterpret_cast<__nv_bfloat162*>(o + c + 2 * K) = bside ? h2 : l2;
}

// in [R,C] f32 -> out [C,3R] bf16 transposed (weights, B-side)
__global__ void split3T_k(const float* __restrict__ in, __nv_bfloat16* __restrict__ out,
                          int R, int C)
{
    __shared__ float t[32][33];
    const int c0 = blockIdx.x * 32, r0 = blockIdx.y * 32;
    const int tx = threadIdx.x, ty = threadIdx.y;
#pragma unroll
    for (int i = 0; i < 4; i++)
        t[ty + i * 8][tx] = in[(long long)(r0 + ty + i * 8) * C + c0 + tx];
    __syncthreads();
#pragma unroll
    for (int i = 0; i < 4; i++) {
        int c = c0 + ty + i * 8;
        int r = r0 + tx;
        float x = t[tx][ty + i * 8];
        __nv_bfloat16 h = __float2bfloat16(x);
        __nv_bfloat16 l = __float2bfloat16(x - __bfloat162float(h));
        __nv_bfloat16* o = out + (long long)c * (3LL * R);
        o[r] = h;
        o[r + R]     = l;
        o[r + 2 * R] = h;
    }
}

// in [R,C] f32 -> out [C,R] fp16 transposed; batched
__global__ void cvtT_h(const float* __restrict__ in, __half* __restrict__ out,
                       int R, int C, long long inBS, long long outBS)
{
    __shared__ float t[32][33];
    const float* ib = in + inBS * blockIdx.z;
    __half* ob = out + outBS * blockIdx.z;
    const int c0 = blockIdx.x * 32, r0 = blockIdx.y * 32;
    const int tx = threadIdx.x, ty = threadIdx.y;
#pragma unroll
    for (int i = 0; i < 4; i++)
        t[ty + i * 8][tx] = ib[(long long)(r0 + ty + i * 8) * C + c0 + tx];
    __syncthreads();
#pragma unroll
    for (int i = 0; i < 4; i++) {
        int c = c0 + ty + i * 8;
        int r = r0 + tx;
        ob[(long long)c * R + r] = __float2half(t[tx][ty + i * 8]);
    }
}

// U = concat(X - Y, X * Y) over L=768 -> fp16 [R,1536]
__global__ void comboh_k(const float* __restrict__ X, const float* __restrict__ Y,
                         __half* __restrict__ out, long long total2)
{
    long long i = (long long)blockIdx.x * blockDim.x + threadIdx.x;
    if (i >= total2) return;
    long long e = i * 2;
    long long r = e / 1536;
    int c = (int)(e - r * 1536);
    float2 x, y, u;
    if (c < 768) {
        x = *reinterpret_cast<const float2*>(X + r * 768 + c);
        y = *reinterpret_cast<const float2*>(Y + r * 768 + c);
        u.x = x.x - y.x; u.y = x.y - y.y;
    } else {
        int j = c - 768;
        x = *reinterpret_cast<const float2*>(X + r * 768 + j);
        y = *reinterpret_cast<const float2*>(Y + r * 768 + j);
        u.x = x.x * y.x; u.y = x.y * y.y;
    }
    *reinterpret_cast<__half2*>(out + r * 1536 + c) = __float22half2_rn(u);
}

// ================= softmax over 1024 columns (+ fused fp16 copy) ==========
__global__ __launch_bounds__(256)
void softmax1024(float* __restrict__ W, __half* __restrict__ Wh)
{
    const long long row = blockIdx.x;
    float* w = W + row * 1024;
    const int t = threadIdx.x;
    float4 v = reinterpret_cast<float4*>(w)[t];
    float m = fmaxf(fmaxf(v.x, v.y), fmaxf(v.z, v.w));
#pragma unroll
    for (int o = 16; o > 0; o >>= 1) m = fmaxf(m, __shfl_xor_sync(0xffffffffu, m, o));
    __shared__ float smax[8], ssum[8];
    if ((t & 31) == 0) smax[t >> 5] = m;
    __syncthreads();
    float bmax = smax[0];
#pragma unroll
    for (int i = 1; i < 8; i++) bmax = fmaxf(bmax, smax[i]);
    v.x = __expf(v.x - bmax); v.y = __expf(v.y - bmax);
    v.z = __expf(v.z - bmax); v.w = __expf(v.w - bmax);
    float s = v.x + v.y + v.z + v.w;
#pragma unroll
    for (int o = 16; o > 0; o >>= 1) s += __shfl_xor_sync(0xffffffffu, s, o);
    if ((t & 31) == 0) ssum[t >> 5] = s;
    __syncthreads();
    float tot = 0.f;
#pragma unroll
    for (int i = 0; i < 8; i++) tot += ssum[i];
    const float inv = 1.f / tot;
    v.x *= inv; v.y *= inv; v.z *= inv; v.w *= inv;
    reinterpret_cast<float4*>(w)[t] = v;
    __half* wh = Wh + row * 1024 + t * 4;
    *reinterpret_cast<__half2*>(wh)     = __float22half2_rn(make_float2(v.x, v.y));
    *reinterpret_cast<__half2*>(wh + 2) = __float22half2_rn(make_float2(v.z, v.w));
}

// ================= launch =================
static inline int blk2(long long total2) { return (int)((total2 + 255) / 256); }

extern "C" void kernel_launch(void* const* d_in, const int* in_sizes, int n_in,
                              void* d_out, int out_size)
{
    (void)in_sizes; (void)n_in; (void)out_size;
    const float* A     = (const float*)d_in[0];
    const float* P     = (const float*)d_in[1];
    const float* G_w   = (const float*)d_in[2];
    const float* G_b   = (const float*)d_in[3];
    const float* fca_w = (const float*)d_in[4];
    const float* fca_b = (const float*)d_in[5];
    const float* fcp_w = (const float*)d_in[6];
    const float* fcp_b = (const float*)d_in[7];
    float* out = (float*)d_out;

    float *Ag, *W, *MP, *MA;
    cudaGetSymbolAddress((void**)&Ag, g_Ag);
    cudaGetSymbolAddress((void**)&W,  g_W);
    cudaGetSymbolAddress((void**)&MP, g_MP);
    cudaGetSymbolAddress((void**)&MA, g_MA);
    __nv_bfloat16 *A3, *P3, *Ag3, *Gt3;
    cudaGetSymbolAddress((void**)&A3,  g_A3);
    cudaGetSymbolAddress((void**)&P3,  g_P3);
    cudaGetSymbolAddress((void**)&Ag3, g_Ag3);
    cudaGetSymbolAddress((void**)&Gt3, g_Gt3);
    __half *Wh, *WTh, *AgTh, *PTh, *U6h, *U7h, *Fah, *Fph;
    cudaGetSymbolAddress((void**)&Wh,   g_Wh);
    cudaGetSymbolAddress((void**)&WTh,  g_WTh);
    cudaGetSymbolAddress((void**)&AgTh, g_AgTh);
    cudaGetSymbolAddress((void**)&PTh,  g_PTh);
    cudaGetSymbolAddress((void**)&U6h,  g_U6h);
    cudaGetSymbolAddress((void**)&U7h,  g_U7h);
    cudaGetSymbolAddress((void**)&Fah,  g_Fah);
    cudaGetSymbolAddress((void**)&Fph,  g_Fph);

    cudaFuncSetAttribute(tgemm<0,false>, cudaFuncAttributeMaxDynamicSharedMemorySize, SMEMSZ);
    cudaFuncSetAttribute(tgemm<1,false>, cudaFuncAttributeMaxDynamicSharedMemorySize, SMEMSZ);
    cudaFuncSetAttribute(tgemm<0,true>,  cudaFuncAttributeMaxDynamicSharedMemorySize, SMEMSZ);
    cudaFuncSetAttribute(tgemm<2,true>,  cudaFuncAttributeMaxDynamicSharedMemorySize, SMEMSZ);

    const dim3 tb(32, 8);

    // --- input conversions ---
    split3_k<<<blk2(16384LL*768/2), 256>>>(A, A3, 768, 0, 16384LL*768/2);          // A (A-side)
    split3_k<<<blk2(32768LL*768/2), 256>>>(P, P3, 768, 0, 32768LL*768/2);          // P (A-side)
    split3T_k<<<dim3(24, 24, 1), tb>>>(G_w, Gt3, 768, 768);                        // G_w^T triple
    cvtT_h<<<dim3(24, 48, 1),  tb>>>(fca_w, Fah, 1536, 768, 0, 0);                 // fca_w^T fp16
    cvtT_h<<<dim3(24, 48, 1),  tb>>>(fcp_w, Fph, 1536, 768, 0, 0);                 // fcp_w^T fp16
    cvtT_h<<<dim3(24, 64, 16), tb>>>(P, PTh, 2048, 768, 2048LL*768, 768LL*2048);   // P^T fp16

    // 1) Ag = A @ G_w + G_b  (bf16 triple-K)
    tgemm<1,false><<<dim3(6, 128, 1), 256, SMEMSZ>>>(
        (const uint16_t*)A3, (const uint16_t*)Gt3, G_b, Ag, 768, 2304, 0, 0, 0);

    split3_k<<<blk2(16384LL*768/2), 256>>>(Ag, Ag3, 768, 1, 16384LL*768/2);        // Ag rows (B-side)
    cvtT_h<<<dim3(24, 32, 16), tb>>>(Ag, AgTh, 1024, 768, 1024LL*768, 768LL*1024); // Ag^T fp16

    // 2) W = P @ Ag^T (per batch, bf16 triple-K)
    tgemm<0,false><<<dim3(8, 16, 16), 256, SMEMSZ>>>(
        (const uint16_t*)P3, (const uint16_t*)Ag3, nullptr, W, 1024, 2304,
        2048LL*2304, 1024LL*2304, 2048LL*1024);

    // 3) softmax over a-dim (+ fused fp16 copy)
    softmax1024<<<BSZ * PLEN, 256>>>(W, Wh);

    cvtT_h<<<dim3(32, 64, 16), tb>>>(W, WTh, 2048, 1024, 2048LL*1024, 1024LL*2048); // W^T fp16

    // 4) MP = W @ Ag (per batch, fp16)
    tgemm<0,true><<<dim3(6, 16, 16), 256, SMEMSZ>>>(
        (const uint16_t*)Wh, (const uint16_t*)AgTh, nullptr, MP, 768, 1024,
        2048LL*1024, 768LL*1024, 2048LL*768);

    // 5) MA = W^T @ P (per batch, fp16)
    tgemm<0,true><<<dim3(6, 8, 16), 256, SMEMSZ>>>(
        (const uint16_t*)WTh, (const uint16_t*)PTh, nullptr, MA, 768, 2048,
        1024LL*2048, 768LL*2048, 1024LL*768);

    // 6) SA = relu(concat(MA-Ag, MA*Ag) @ fca_w + fca_b)  (fp16)
    comboh_k<<<blk2(16384LL*1536/2), 256>>>(MA, Ag, U6h, 16384LL*1536/2);
    tgemm<2,true><<<dim3(6, 128, 1), 256, SMEMSZ>>>(
        (const uint16_t*)U6h, (const uint16_t*)Fah, fca_b, out, 768, 1536, 0, 0, 0);

    // 7) SP = relu(concat(MP-P, MP*P) @ fcp_w + fcp_b)  (fp16)
    comboh_k<<<blk2(32768LL*1536/2), 256>>>(MP, P, U7h, 32768LL*1536/2);
    tgemm<2,true><<<dim3(6, 256, 1), 256, SMEMSZ>>>(
        (const uint16_t*)U7h, (const uint16_t*)Fph, fcp_b,
        out + 16384LL * 768, 768, 1536, 0, 0, 0);
}

// round 5
// speedup vs baseline: 4.3552x; 1.0566x over previous
#include <cuda_runtime.h>
#include <cuda_bf16.h>
#include <cuda_fp16.h>
#include <cstdint>

// ---------------- problem constants ----------------
#define BSZ   16
#define ALEN 1024
#define PLEN 2048
#define LDIM 768

// ================= scratch (device globals) =================
__device__ __align__(256) float g_Ag[(size_t)BSZ * ALEN * LDIM];
__device__ __align__(256) float g_W [(size_t)BSZ * PLEN * ALEN];

// bf16 triple-K operand buffers (logit chain only)
__device__ __align__(256) __nv_bfloat16 g_A3 [(size_t)16384 * 2304];
__device__ __align__(256) __nv_bfloat16 g_P3 [(size_t)32768 * 2304];
__device__ __align__(256) __nv_bfloat16 g_Ag3[(size_t)16384 * 2304];
__device__ __align__(256) __nv_bfloat16 g_Gt3[(size_t)768 * 2304];

// fp16 single operand buffers (post-softmax chain)
__device__ __align__(256) __half g_Wh  [(size_t)32768 * 1024];
__device__ __align__(256) __half g_WTh [(size_t)16 * 1024 * 2048];
__device__ __align__(256) __half g_AgTh[(size_t)16 * 768 * 1024];
__device__ __align__(256) __half g_PTh [(size_t)16 * 768 * 2048];
__device__ __align__(256) __half g_U6h [(size_t)16384 * 1536];
__device__ __align__(256) __half g_U7h [(size_t)32768 * 1536];
__device__ __align__(256) __half g_Fah [(size_t)768 * 1536];
__device__ __align__(256) __half g_Fph [(size_t)768 * 1536];

// ================= helpers =================
__device__ __forceinline__ uint32_t smem_u32(const void* p) {
    uint32_t a;
    asm("{ .reg .u64 t; cvta.to.shared.u64 t, %1; cvt.u32.u64 %0, t; }" : "=r"(a) : "l"(p));
    return a;
}

#define LDSM4(r0, r1, r2, r3, a)                                              \
    asm volatile("ldmatrix.sync.aligned.m8n8.x4.shared.b16 {%0,%1,%2,%3}, [%4];" \
                 : "=r"(r0), "=r"(r1), "=r"(r2), "=r"(r3) : "r"(a))

__device__ __forceinline__ void mma_bf16(float* c, uint32_t a0, uint32_t a1, uint32_t a2,
                                         uint32_t a3, uint32_t b0, uint32_t b1) {
    asm volatile("mma.sync.aligned.m16n8k16.row.col.f32.bf16.bf16.f32 "
                 "{%0,%1,%2,%3}, {%4,%5,%6,%7}, {%8,%9}, {%0,%1,%2,%3};"
                 : "+f"(c[0]), "+f"(c[1]), "+f"(c[2]), "+f"(c[3])
                 : "r"(a0), "r"(a1), "r"(a2), "r"(a3), "r"(b0), "r"(b1));
}
__device__ __forceinline__ void mma_fp16(float* c, uint32_t a0, uint32_t a1, uint32_t a2,
                                         uint32_t a3, uint32_t b0, uint32_t b1) {
    asm volatile("mma.sync.aligned.m16n8k16.row.col.f32.f16.f16.f32 "
                 "{%0,%1,%2,%3}, {%4,%5,%6,%7}, {%8,%9}, {%0,%1,%2,%3};"
                 : "+f"(c[0]), "+f"(c[1]), "+f"(c[2]), "+f"(c[3])
                 : "r"(a0), "r"(a1), "r"(a2), "r"(a3), "r"(b0), "r"(b1));
}

// ================= tensor-core GEMM (mma.sync) =================
// C[M,N](f32) = A[M,Kp] * B[N,Kp]^T, 16-bit operands, 128x128 tile, K-chunk 32,
// 3-stage cp.async pipeline.
// EPI: 0 = fp32 C
//      1 = fp32 C + bias
//      2 = fp32 relu(C + bias)
//      3 = combo: fp16 out2[r, c] = C - aux[r,c]; out2[r, c+N] = C * aux[r,c]
//          (out2 row stride 2N, batch stride 2*bsC; fp32 C not written)
//      4 = Ag mode: fp32 C = acc + bias, plus bf16 triple out2[r, c]=hi,
//          [r,c+N]=lo, [r,c+2N]=hi (row stride 3N; non-batched)
#define TSTRIDE 80
#define TILEB   (128 * TSTRIDE)
#define STAGEB  (2 * TILEB)
#define NSTAGE  3
#define SMEMSZ  (NSTAGE * STAGEB)   // 61440 B

__device__ __forceinline__ void ld_tile(uint32_t sdst, const char* g, int rowB, int tid) {
#pragma unroll
    for (int i = 0; i < 2; i++) {
        int idx = i * 256 + tid;
        int row = idx >> 2;
        int c = idx & 3;
        uint32_t so = sdst + row * TSTRIDE + c * 16;
        asm volatile("cp.async.cg.shared.global [%0], [%1], 16;\n"
                     :: "r"(so), "l"(g + (long long)row * rowB + c * 16));
    }
}

template<int EPI, bool FP16>
__global__ __launch_bounds__(256)
void tgemm(const uint16_t* __restrict__ Aop,
           const uint16_t* __restrict__ Bop,
           const float* __restrict__ bias,
           const float* __restrict__ aux,
           float* __restrict__ Cout,
           void* __restrict__ out2,
           int N, int Kp,
           long long bsA, long long bsB, long long bsC)
{
    extern __shared__ __align__(128) char smem[];
    const uint32_t sbase = smem_u32(smem);
    const int tid  = threadIdx.x;
    const int wid  = tid >> 5;
    const int lane = tid & 31;
    const int wm = wid & 1;
    const int wn = wid >> 1;

    const int rowB = Kp * 2;
    const char* Abase = ((const char*)Aop) + 2LL * (bsA * blockIdx.z + (long long)blockIdx.y * 128 * Kp);
    const char* Bbase = ((const char*)Bop) + 2LL * (bsB * blockIdx.z + (long long)blockIdx.x * 128 * Kp);

    const int ntiles = Kp >> 5;

    float c[4][4][4];
#pragma unroll
    for (int i = 0; i < 4; i++)
#pragma unroll
        for (int j = 0; j < 4; j++) {
            c[i][j][0] = 0.f; c[i][j][1] = 0.f; c[i][j][2] = 0.f; c[i][j][3] = 0.f;
        }

#pragma unroll
    for (int s = 0; s < 2; s++) {
        ld_tile(sbase + s * STAGEB,         Abase + s * 64, rowB, tid);
        ld_tile(sbase + s * STAGEB + TILEB, Bbase + s * 64, rowB, tid);
        asm volatile("cp.async.commit_group;\n" ::: "memory");
    }

    const uint32_t aoff = (uint32_t)((wm * 64 + (lane & 15)) * TSTRIDE + ((lane >> 4) << 4));
    const uint32_t boff = (uint32_t)((wn * 32 + ((lane >> 4) << 3) + (lane & 7)) * TSTRIDE
                                     + (((lane >> 3) & 1) << 4));

    for (int ks = 0; ks < ntiles; ks++) {
        const int b = ks % NSTAGE;
        asm volatile("cp.async.wait_group 1;\n" ::: "memory");
        __syncthreads();

        const uint32_t sA = sbase + b * STAGEB;
        const uint32_t sB = sA + TILEB;

#pragma unroll
        for (int kk = 0; kk < 2; kk++) {
            uint32_t bf[8];
            uint32_t ba = sB + boff + kk * 32;
            LDSM4(bf[0], bf[1], bf[2], bf[3], ba);
            LDSM4(bf[4], bf[5], bf[6], bf[7], ba + 16 * TSTRIDE);
#pragma unroll
            for (int mt = 0; mt < 4; mt++) {
                uint32_t a0, a1, a2, a3;
                LDSM4(a0, a1, a2, a3, sA + aoff + mt * 16 * TSTRIDE + kk * 32);
                if (FP16) {
                    mma_fp16(c[mt][0], a0, a1, a2, a3, bf[0], bf[1]);
                    mma_fp16(c[mt][1], a0, a1, a2, a3, bf[2], bf[3]);
                    mma_fp16(c[mt][2], a0, a1, a2, a3, bf[4], bf[5]);
                    mma_fp16(c[mt][3], a0, a1, a2, a3, bf[6], bf[7]);
                } else {
                    mma_bf16(c[mt][0], a0, a1, a2, a3, bf[0], bf[1]);
                    mma_bf16(c[mt][1], a0, a1, a2, a3, bf[2], bf[3]);
                    mma_bf16(c[mt][2], a0, a1, a2, a3, bf[4], bf[5]);
                    mma_bf16(c[mt][3], a0, a1, a2, a3, bf[6], bf[7]);
                }
            }
        }

        const int kl = ks + 2;
        if (kl < ntiles) {
            const int bl = kl % NSTAGE;
            ld_tile(sbase + bl * STAGEB,         Abase + kl * 64, rowB, tid);
            ld_tile(sbase + bl * STAGEB + TILEB, Bbase + kl * 64, rowB, tid);
        }
        asm volatile("cp.async.commit_group;\n" ::: "memory");
    }

    // ---- epilogue ----
    const long long bz = blockIdx.z;
    const int row0 = blockIdx.y * 128 + wm * 64 + (lane >> 2);
    const int col0 = blockIdx.x * 128 + wn * 32 + (lane & 3) * 2;

#pragma unroll
    for (int mt = 0; mt < 4; mt++) {
#pragma unroll
        for (int nt = 0; nt < 4; nt++) {
            const int r = row0 + mt * 16;
            const int cl = col0 + nt * 8;
            float2 v0 = make_float2(c[mt][nt][0], c[mt][nt][1]);
            float2 v1 = make_float2(c[mt][nt][2], c[mt][nt][3]);

            if (EPI == 3) {
                const float* Yb = aux + bsC * bz;
                __half* Ub = ((__half*)out2) + 2 * bsC * bz;
                const int ustr = 2 * N;
                float2 y0 = *reinterpret_cast<const float2*>(Yb + (long long)r * N + cl);
                float2 y1 = *reinterpret_cast<const float2*>(Yb + (long long)(r + 8) * N + cl);
                *reinterpret_cast<__half2*>(Ub + (long long)r * ustr + cl) =
                    __float22half2_rn(make_float2(v0.x - y0.x, v0.y - y0.y));
                *reinterpret_cast<__half2*>(Ub + (long long)r * ustr + cl + N) =
                    __float22half2_rn(make_float2(v0.x * y0.x, v0.y * y0.y));
                *reinterpret_cast<__half2*>(Ub + (long long)(r + 8) * ustr + cl) =
                    __float22half2_rn(make_float2(v1.x - y1.x, v1.y - y1.y));
                *reinterpret_cast<__half2*>(Ub + (long long)(r + 8) * ustr + cl + N) =
                    __float22half2_rn(make_float2(v1.x * y1.x, v1.y * y1.y));
                continue;
            }

            if (EPI == 1 || EPI == 2 || EPI == 4) {
                float2 bv = *reinterpret_cast<const float2*>(bias + cl);
                v0.x += bv.x; v0.y += bv.y; v1.x += bv.x; v1.y += bv.y;
            }
            if (EPI == 2) {
                v0.x = fmaxf(v0.x, 0.f); v0.y = fmaxf(v0.y, 0.f);
                v1.x = fmaxf(v1.x, 0.f); v1.y = fmaxf(v1.y, 0.f);
            }
            float* Cb = Cout + bsC * bz;
            *reinterpret_cast<float2*>(Cb + (long long)r * N + cl)       = v0;
            *reinterpret_cast<float2*>(Cb + (long long)(r + 8) * N + cl) = v1;

            if (EPI == 4) {
                __nv_bfloat16* T = (__nv_bfloat16*)out2;
                const int tstr = 3 * N;
                __nv_bfloat162 h0 = __float22bfloat162_rn(v0);
                __nv_bfloat162 h1 = __float22bfloat162_rn(v1);
                __nv_bfloat162 l0 = __float22bfloat162_rn(
                    make_float2(v0.x - __bfloat162float(h0.x), v0.y - __bfloat162float(h0.y)));
                __nv_bfloat162 l1 = __float22bfloat162_rn(
                    make_float2(v1.x - __bfloat162float(h1.x), v1.y - __bfloat162float(h1.y)));
                *reinterpret_cast<__nv_bfloat162*>(T + (long long)r * tstr + cl)          = h0;
                *reinterpret_cast<__nv_bfloat162*>(T + (long long)r * tstr + cl + N)      = l0;
                *reinterpret_cast<__nv_bfloat162*>(T + (long long)r * tstr + cl + 2 * N)  = h0;
                *reinterpret_cast<__nv_bfloat162*>(T + (long long)(r + 8) * tstr + cl)         = h1;
                *reinterpret_cast<__nv_bfloat162*>(T + (long long)(r + 8) * tstr + cl + N)     = l1;
                *reinterpret_cast<__nv_bfloat162*>(T + (long long)(r + 8) * tstr + cl + 2 * N) = h1;
            }
        }
    }
}

// ================= conversion kernels =================
__device__ __forceinline__ void hilo2(float2 v, __nv_bfloat162& h2, __nv_bfloat162& l2) {
    h2 = __float22bfloat162_rn(v);
    float2 r;
    r.x = v.x - __bfloat162float(h2.x);
    r.y = v.y - __bfloat162float(h2.y);
    l2 = __float22bfloat162_rn(r);
}

// in [R,K] f32 -> out [R,3K] bf16 (A-side: hi,hi,lo)
__global__ void split3_k(const float* __restrict__ in, __nv_bfloat16* __restrict__ out,
                         int K, long long total2)
{
    long long i = (long long)blockIdx.x * blockDim.x + threadIdx.x;
    if (i >= total2) return;
    long long e = i * 2;
    long long r = e / K;
    int c = (int)(e - r * K);
    float2 v = *reinterpret_cast<const float2*>(in + e);
    __nv_bfloat162 h2, l2;
    hilo2(v, h2, l2);
    __nv_bfloat16* o = out + r * (3LL * K);
    *reinterpret_cast<__nv_bfloat162*>(o + c)         = h2;
    *reinterpret_cast<__nv_bfloat162*>(o + c + K)     = h2;
    *reinterpret_cast<__nv_bfloat162*>(o + c + 2 * K) = l2;
}

// in [R,C] f32 -> out [C,3R] bf16 transposed (weights, B-side: hi,lo,hi)
__global__ void split3T_k(const float* __restrict__ in, __nv_bfloat16* __restrict__ out,
                          int R, int C)
{
    __shared__ float t[32][33];
    const int c0 = blockIdx.x * 32, r0 = blockIdx.y * 32;
    const int tx = threadIdx.x, ty = threadIdx.y;
#pragma unroll
    for (int i = 0; i < 4; i++)
        t[ty + i * 8][tx] = in[(long long)(r0 + ty + i * 8) * C + c0 + tx];
    __syncthreads();
#pragma unroll
    for (int i = 0; i < 4; i++) {
        int c = c0 + ty + i * 8;
        int r = r0 + tx;
        float x = t[tx][ty + i * 8];
        __nv_bfloat16 h = __float2bfloat16(x);
        __nv_bfloat16 l = __float2bfloat16(x - __bfloat162float(h));
        __nv_bfloat16* o = out + (long long)c * (3LL * R);
        o[r] = h;
        o[r + R]     = l;
        o[r + 2 * R] = h;
    }
}

// in [R,C] f32 -> out [C,R] fp16 transposed; batched
__global__ void cvtT_h(const float* __restrict__ in, __half* __restrict__ out,
                       int R, int C, long long inBS, long long outBS)
{
    __shared__ float t[32][33];
    const float* ib = in + inBS * blockIdx.z;
    __half* ob = out + outBS * blockIdx.z;
    const int c0 = blockIdx.x * 32, r0 = blockIdx.y * 32;
    const int tx = threadIdx.x, ty = threadIdx.y;
#pragma unroll
    for (int i = 0; i < 4; i++)
        t[ty + i * 8][tx] = ib[(long long)(r0 + ty + i * 8) * C + c0 + tx];
    __syncthreads();
#pragma unroll
    for (int i = 0; i < 4; i++) {
        int c = c0 + ty + i * 8;
        int r = r0 + tx;
        ob[(long long)c * R + r] = __float2half(t[tx][ty + i * 8]);
    }
}

// fp16 transpose: in [R,C] -> out [C,R]; batched; 64x64 tiles; block (32,8)
__global__ void cvtT_hh(const __half* __restrict__ in, __half* __restrict__ out,
                        int R, int C, long long inBS, long long outBS)
{
    __shared__ __half2 t[64][33];
    const __half* ib = in + inBS * blockIdx.z;
    __half* ob = out + outBS * blockIdx.z;
    const int c0 = blockIdx.x * 64, r0 = blockIdx.y * 64;
    const int tx = threadIdx.x, ty = threadIdx.y;
#pragma unroll
    for (int i = 0; i < 8; i++) {
        int row = ty + i * 8;
        t[row][tx] = reinterpret_cast<const __half2*>(ib + (long long)(r0 + row) * C + c0)[tx];
    }
    __syncthreads();
#pragma unroll
    for (int i = 0; i < 8; i++) {
        int cc = ty + i * 8;                 // column within tile = output row
        __half2 p0 = t[2 * tx][cc >> 1];
        __half2 p1 = t[2 * tx + 1][cc >> 1];
        __half x0 = (cc & 1) ? __high2half(p0) : __low2half(p0);
        __half x1 = (cc & 1) ? __high2half(p1) : __low2half(p1);
        reinterpret_cast<__half2*>(ob + (long long)(c0 + cc) * R + r0)[tx] =
            __halves2half2(x0, x1);
    }
}

// ================= softmax over 1024 columns -> fp16 ==========
__global__ __launch_bounds__(256)
void softmax1024(const float* __restrict__ W, __half* __restrict__ Wh)
{
    const long long row = blockIdx.x;
    const float* w = W + row * 1024;
    const int t = threadIdx.x;
    float4 v = reinterpret_cast<const float4*>(w)[t];
    float m = fmaxf(fmaxf(v.x, v.y), fmaxf(v.z, v.w));
#pragma unroll
    for (int o = 16; o > 0; o >>= 1) m = fmaxf(m, __shfl_xor_sync(0xffffffffu, m, o));
    __shared__ float smax[8], ssum[8];
    if ((t & 31) == 0) smax[t >> 5] = m;
    __syncthreads();
    float bmax = smax[0];
#pragma unroll
    for (int i = 1; i < 8; i++) bmax = fmaxf(bmax, smax[i]);
    v.x = __expf(v.x - bmax); v.y = __expf(v.y - bmax);
    v.z = __expf(v.z - bmax); v.w = __expf(v.w - bmax);
    float s = v.x + v.y + v.z + v.w;
#pragma unroll
    for (int o = 16; o > 0; o >>= 1) s += __shfl_xor_sync(0xffffffffu, s, o);
    if ((t & 31) == 0) ssum[t >> 5] = s;
    __syncthreads();
    float tot = 0.f;
#pragma unroll
    for (int i = 0; i < 8; i++) tot += ssum[i];
    const float inv = 1.f / tot;
    __half* wh = Wh + row * 1024 + t * 4;
    *reinterpret_cast<__half2*>(wh)     = __float22half2_rn(make_float2(v.x * inv, v.y * inv));
    *reinterpret_cast<__half2*>(wh + 2) = __float22half2_rn(make_float2(v.z * inv, v.w * inv));
}

// ================= launch =================
static inline int blk2(long long total2) { return (int)((total2 + 255) / 256); }

extern "C" void kernel_launch(void* const* d_in, const int* in_sizes, int n_in,
                              void* d_out, int out_size)
{
    (void)in_sizes; (void)n_in; (void)out_size;
    const float* A     = (const float*)d_in[0];
    const float* P     = (const float*)d_in[1];
    const float* G_w   = (const float*)d_in[2];
    const float* G_b   = (const float*)d_in[3];
    const float* fca_w = (const float*)d_in[4];
    const float* fca_b = (const float*)d_in[5];
    const float* fcp_w = (const float*)d_in[6];
    const float* fcp_b = (const float*)d_in[7];
    float* out = (float*)d_out;

    float *Ag, *W;
    cudaGetSymbolAddress((void**)&Ag, g_Ag);
    cudaGetSymbolAddress((void**)&W,  g_W);
    __nv_bfloat16 *A3, *P3, *Ag3, *Gt3;
    cudaGetSymbolAddress((void**)&A3,  g_A3);
    cudaGetSymbolAddress((void**)&P3,  g_P3);
    cudaGetSymbolAddress((void**)&Ag3, g_Ag3);
    cudaGetSymbolAddress((void**)&Gt3, g_Gt3);
    __half *Wh, *WTh, *AgTh, *PTh, *U6h, *U7h, *Fah, *Fph;
    cudaGetSymbolAddress((void**)&Wh,   g_Wh);
    cudaGetSymbolAddress((void**)&WTh,  g_WTh);
    cudaGetSymbolAddress((void**)&AgTh, g_AgTh);
    cudaGetSymbolAddress((void**)&PTh,  g_PTh);
    cudaGetSymbolAddress((void**)&U6h,  g_U6h);
    cudaGetSymbolAddress((void**)&U7h,  g_U7h);
    cudaGetSymbolAddress((void**)&Fah,  g_Fah);
    cudaGetSymbolAddress((void**)&Fph,  g_Fph);

    cudaFuncSetAttribute(tgemm<0,false>, cudaFuncAttributeMaxDynamicSharedMemorySize, SMEMSZ);
    cudaFuncSetAttribute(tgemm<4,false>, cudaFuncAttributeMaxDynamicSharedMemorySize, SMEMSZ);
    cudaFuncSetAttribute(tgemm<3,true>,  cudaFuncAttributeMaxDynamicSharedMemorySize, SMEMSZ);
    cudaFuncSetAttribute(tgemm<2,true>,  cudaFuncAttributeMaxDynamicSharedMemorySize, SMEMSZ);

    const dim3 tb(32, 8);

    // --- input conversions ---
    split3_k<<<blk2(16384LL*768/2), 256>>>(A, A3, 768, 16384LL*768/2);
    split3_k<<<blk2(32768LL*768/2), 256>>>(P, P3, 768, 32768LL*768/2);
    split3T_k<<<dim3(24, 24, 1), tb>>>(G_w, Gt3, 768, 768);
    cvtT_h<<<dim3(24, 48, 1),  tb>>>(fca_w, Fah, 1536, 768, 0, 0);
    cvtT_h<<<dim3(24, 48, 1),  tb>>>(fcp_w, Fph, 1536, 768, 0, 0);
    cvtT_h<<<dim3(24, 64, 16), tb>>>(P, PTh, 2048, 768, 2048LL*768, 768LL*2048);

    // 1) Ag = A @ G_w + G_b  (bf16 triple-K) -> fp32 Ag + bf16 triple Ag3
    tgemm<4,false><<<dim3(6, 128, 1), 256, SMEMSZ>>>(
        (const uint16_t*)A3, (const uint16_t*)Gt3, G_b, nullptr, Ag, Ag3,
        768, 2304, 0, 0, 0);

    cvtT_h<<<dim3(24, 32, 16), tb>>>(Ag, AgTh, 1024, 768, 1024LL*768, 768LL*1024);

    // 2) W = P @ Ag^T (per batch, bf16 triple-K) -> fp32 logits
    tgemm<0,false><<<dim3(8, 16, 16), 256, SMEMSZ>>>(
        (const uint16_t*)P3, (const uint16_t*)Ag3, nullptr, nullptr, W, nullptr,
        1024, 2304, 2048LL*2304, 1024LL*2304, 2048LL*1024);

    // 3) softmax over a-dim -> fp16 Wh only
    softmax1024<<<BSZ * PLEN, 256>>>(W, Wh);

    // fp16 transpose Wh -> WTh (per batch: [2048,1024] -> [1024,2048])
    cvtT_hh<<<dim3(16, 32, 16), tb>>>(Wh, WTh, 2048, 1024, 2048LL*1024, 1024LL*2048);

    // 4) MP = W @ Ag (per batch, fp16), fused combo with P -> U7h
    tgemm<3,true><<<dim3(6, 16, 16), 256, SMEMSZ>>>(
        (const uint16_t*)Wh, (const uint16_t*)AgTh, nullptr, P, nullptr, U7h,
        768, 1024, 2048LL*1024, 768LL*1024, 2048LL*768);

    // 5) MA = W^T @ P (per batch, fp16), fused combo with Ag -> U6h
    tgemm<3,true><<<dim3(6, 8, 16), 256, SMEMSZ>>>(
        (const uint16_t*)WTh, (const uint16_t*)PTh, nullptr, Ag, nullptr, U6h,
        768, 2048, 1024LL*2048, 768LL*2048, 1024LL*768);

    // 6) SA = relu(U6 @ fca_w + fca_b)
    tgemm<2,true><<<dim3(6, 128, 1), 256, SMEMSZ>>>(
        (const uint16_t*)U6h, (const uint16_t*)Fah, fca_b, nullptr, out, nullptr,
        768, 1536, 0, 0, 0);

    // 7) SP = relu(U7 @ fcp_w + fcp_b)
    tgemm<2,true><<<dim3(6, 256, 1), 256, SMEMSZ>>>(
        (const uint16_t*)U7h, (const uint16_t*)Fph, fcp_b, nullptr,
        out + 16384LL * 768, nullptr, 768, 1536, 0, 0, 0);
}

// round 6
// speedup vs baseline: 4.8103x; 1.1045x over previous
#include <cuda_runtime.h>
#include <cuda_bf16.h>
#include <cuda_fp16.h>
#include <cstdint>

// ---------------- problem constants ----------------
#define BSZ   16
#define ALEN 1024
#define PLEN 2048
#define LDIM 768

// ================= scratch (device globals) =================
__device__ __align__(256) float g_Ag[(size_t)BSZ * ALEN * LDIM];
__device__ __align__(256) float g_W [(size_t)BSZ * PLEN * ALEN];

// bf16 triple-K operand buffers (logit chain only)
__device__ __align__(256) __nv_bfloat16 g_A3 [(size_t)16384 * 2304];
__device__ __align__(256) __nv_bfloat16 g_P3 [(size_t)32768 * 2304];
__device__ __align__(256) __nv_bfloat16 g_Ag3[(size_t)16384 * 2304];
__device__ __align__(256) __nv_bfloat16 g_Gt3[(size_t)768 * 2304];

// fp16 single operand buffers (post-softmax chain)
__device__ __align__(256) __half g_Wh  [(size_t)32768 * 1024];
__device__ __align__(256) __half g_WTh [(size_t)16 * 1024 * 2048];
__device__ __align__(256) __half g_AgTh[(size_t)16 * 768 * 1024];
__device__ __align__(256) __half g_PTh [(size_t)16 * 768 * 2048];
__device__ __align__(256) __half g_U6h [(size_t)16384 * 1536];
__device__ __align__(256) __half g_U7h [(size_t)32768 * 1536];
__device__ __align__(256) __half g_Fah [(size_t)768 * 1536];
__device__ __align__(256) __half g_Fph [(size_t)768 * 1536];

// ================= helpers =================
__device__ __forceinline__ uint32_t smem_u32(const void* p) {
    uint32_t a;
    asm("{ .reg .u64 t; cvta.to.shared.u64 t, %1; cvt.u32.u64 %0, t; }" : "=r"(a) : "l"(p));
    return a;
}

#define LDSM4(r0, r1, r2, r3, a)                                              \
    asm volatile("ldmatrix.sync.aligned.m8n8.x4.shared.b16 {%0,%1,%2,%3}, [%4];" \
                 : "=r"(r0), "=r"(r1), "=r"(r2), "=r"(r3) : "r"(a))

__device__ __forceinline__ void mma_bf16(float* c, uint32_t a0, uint32_t a1, uint32_t a2,
                                         uint32_t a3, uint32_t b0, uint32_t b1) {
    asm volatile("mma.sync.aligned.m16n8k16.row.col.f32.bf16.bf16.f32 "
                 "{%0,%1,%2,%3}, {%4,%5,%6,%7}, {%8,%9}, {%0,%1,%2,%3};"
                 : "+f"(c[0]), "+f"(c[1]), "+f"(c[2]), "+f"(c[3])
                 : "r"(a0), "r"(a1), "r"(a2), "r"(a3), "r"(b0), "r"(b1));
}
__device__ __forceinline__ void mma_fp16(float* c, uint32_t a0, uint32_t a1, uint32_t a2,
                                         uint32_t a3, uint32_t b0, uint32_t b1) {
    asm volatile("mma.sync.aligned.m16n8k16.row.col.f32.f16.f16.f32 "
                 "{%0,%1,%2,%3}, {%4,%5,%6,%7}, {%8,%9}, {%0,%1,%2,%3};"
                 : "+f"(c[0]), "+f"(c[1]), "+f"(c[2]), "+f"(c[3])
                 : "r"(a0), "r"(a1), "r"(a2), "r"(a3), "r"(b0), "r"(b1));
}

// ================= tensor-core GEMM (mma.sync) =================
// C[M,N](f32) = A[M,Kp] * B[N,Kp]^T, 16-bit operands.
// 128x128 block tile, 128 threads (2x2 warps, 64x64 warp tile),
// K-chunk 32, 4-stage cp.async pipeline (prefetch depth 3).
// EPI: 0 fp32 C | 1 +bias | 2 relu(+bias)
//      3 combo: fp16 out2[r,c]=C-aux, out2[r,c+N]=C*aux (stride 2N)
//      4 Ag: fp32 C=acc+bias + bf16 triple (hi,lo,hi; stride 3N)
#define TSTRIDE 80
#define TILEB   (128 * TSTRIDE)
#define STAGEB  (2 * TILEB)
#define NSTAGE  4
#define SMEMSZ  (NSTAGE * STAGEB)   // 81920 B

__device__ __forceinline__ void ld_tile(uint32_t sdst, const char* g, int rowB, int tid) {
#pragma unroll
    for (int i = 0; i < 4; i++) {
        int idx = i * 128 + tid;
        int row = idx >> 2;
        int c = idx & 3;
        uint32_t so = sdst + row * TSTRIDE + c * 16;
        asm volatile("cp.async.cg.shared.global [%0], [%1], 16;\n"
                     :: "r"(so), "l"(g + (long long)row * rowB + c * 16));
    }
}

template<int EPI, bool FP16>
__global__ __launch_bounds__(128, 2)
void tgemm(const uint16_t* __restrict__ Aop,
           const uint16_t* __restrict__ Bop,
           const float* __restrict__ bias,
           const float* __restrict__ aux,
           float* __restrict__ Cout,
           void* __restrict__ out2,
           int N, int Kp,
           long long bsA, long long bsB, long long bsC)
{
    extern __shared__ __align__(128) char smem[];
    const uint32_t sbase = smem_u32(smem);
    const int tid  = threadIdx.x;
    const int wid  = tid >> 5;
    const int lane = tid & 31;
    const int wm = wid & 1;     // 2 warps in m
    const int wn = wid >> 1;    // 2 warps in n

    const int rowB = Kp * 2;
    const char* Abase = ((const char*)Aop) + 2LL * (bsA * blockIdx.z + (long long)blockIdx.y * 128 * Kp);
    const char* Bbase = ((const char*)Bop) + 2LL * (bsB * blockIdx.z + (long long)blockIdx.x * 128 * Kp);

    const int ntiles = Kp >> 5;

    float c[4][8][4];
#pragma unroll
    for (int i = 0; i < 4; i++)
#pragma unroll
        for (int j = 0; j < 8; j++) {
            c[i][j][0] = 0.f; c[i][j][1] = 0.f; c[i][j][2] = 0.f; c[i][j][3] = 0.f;
        }

    // prologue: 3 stages in flight
#pragma unroll
    for (int s = 0; s < 3; s++) {
        ld_tile(sbase + s * STAGEB,         Abase + s * 64, rowB, tid);
        ld_tile(sbase + s * STAGEB + TILEB, Bbase + s * 64, rowB, tid);
        asm volatile("cp.async.commit_group;\n" ::: "memory");
    }

    const uint32_t aoff = (uint32_t)((wm * 64 + (lane & 15)) * TSTRIDE + ((lane >> 4) << 4));
    const uint32_t boff = (uint32_t)((wn * 64 + ((lane >> 4) << 3) + (lane & 7)) * TSTRIDE
                                     + (((lane >> 3) & 1) << 4));

    for (int ks = 0; ks < ntiles; ks++) {
        const int b = ks % NSTAGE;
        asm volatile("cp.async.wait_group 2;\n" ::: "memory");
        __syncthreads();

        const uint32_t sA = sbase + b * STAGEB;
        const uint32_t sB = sA + TILEB;

#pragma unroll
        for (int kk = 0; kk < 2; kk++) {
            uint32_t bf[16];
            uint32_t ba = sB + boff + kk * 32;
#pragma unroll
            for (int bi = 0; bi < 4; bi++)
                LDSM4(bf[bi * 4 + 0], bf[bi * 4 + 1], bf[bi * 4 + 2], bf[bi * 4 + 3],
                      ba + bi * 16 * TSTRIDE);
#pragma unroll
            for (int mt = 0; mt < 4; mt++) {
                uint32_t a0, a1, a2, a3;
                LDSM4(a0, a1, a2, a3, sA + aoff + mt * 16 * TSTRIDE + kk * 32);
#pragma unroll
                for (int bi = 0; bi < 4; bi++) {
                    if (FP16) {
                        mma_fp16(c[mt][2 * bi],     a0, a1, a2, a3, bf[bi * 4 + 0], bf[bi * 4 + 1]);
                        mma_fp16(c[mt][2 * bi + 1], a0, a1, a2, a3, bf[bi * 4 + 2], bf[bi * 4 + 3]);
                    } else {
                        mma_bf16(c[mt][2 * bi],     a0, a1, a2, a3, bf[bi * 4 + 0], bf[bi * 4 + 1]);
                        mma_bf16(c[mt][2 * bi + 1], a0, a1, a2, a3, bf[bi * 4 + 2], bf[bi * 4 + 3]);
                    }
                }
            }
        }

        const int kl = ks + 3;
        if (kl < ntiles) {
            const int bl = kl % NSTAGE;
            ld_tile(sbase + bl * STAGEB,         Abase + kl * 64, rowB, tid);
            ld_tile(sbase + bl * STAGEB + TILEB, Bbase + kl * 64, rowB, tid);
        }
        asm volatile("cp.async.commit_group;\n" ::: "memory");
    }

    // ---- epilogue ----
    const long long bz = blockIdx.z;
    const int row0 = blockIdx.y * 128 + wm * 64 + (lane >> 2);
    const int col0 = blockIdx.x * 128 + wn * 64 + (lane & 3) * 2;

#pragma unroll
    for (int mt = 0; mt < 4; mt++) {
#pragma unroll
        for (int nt = 0; nt < 8; nt++) {
            const int r = row0 + mt * 16;
            const int cl = col0 + nt * 8;
            float2 v0 = make_float2(c[mt][nt][0], c[mt][nt][1]);
            float2 v1 = make_float2(c[mt][nt][2], c[mt][nt][3]);

            if (EPI == 3) {
                const float* Yb = aux + bsC * bz;
                __half* Ub = ((__half*)out2) + 2 * bsC * bz;
                const int ustr = 2 * N;
                float2 y0 = *reinterpret_cast<const float2*>(Yb + (long long)r * N + cl);
                float2 y1 = *reinterpret_cast<const float2*>(Yb + (long long)(r + 8) * N + cl);
                *reinterpret_cast<__half2*>(Ub + (long long)r * ustr + cl) =
                    __float22half2_rn(make_float2(v0.x - y0.x, v0.y - y0.y));
                *reinterpret_cast<__half2*>(Ub + (long long)r * ustr + cl + N) =
                    __float22half2_rn(make_float2(v0.x * y0.x, v0.y * y0.y));
                *reinterpret_cast<__half2*>(Ub + (long long)(r + 8) * ustr + cl) =
                    __float22half2_rn(make_float2(v1.x - y1.x, v1.y - y1.y));
                *reinterpret_cast<__half2*>(Ub + (long long)(r + 8) * ustr + cl + N) =
                    __float22half2_rn(make_float2(v1.x * y1.x, v1.y * y1.y));
                continue;
            }

            if (EPI == 1 || EPI == 2 || EPI == 4) {
                float2 bv = *reinterpret_cast<const float2*>(bias + cl);
                v0.x += bv.x; v0.y += bv.y; v1.x += bv.x; v1.y += bv.y;
            }
            if (EPI == 2) {
                v0.x = fmaxf(v0.x, 0.f); v0.y = fmaxf(v0.y, 0.f);
                v1.x = fmaxf(v1.x, 0.f); v1.y = fmaxf(v1.y, 0.f);
            }
            float* Cb = Cout + bsC * bz;
            *reinterpret_cast<float2*>(Cb + (long long)r * N + cl)       = v0;
            *reinterpret_cast<float2*>(Cb + (long long)(r + 8) * N + cl) = v1;

            if (EPI == 4) {
                __nv_bfloat16* T = (__nv_bfloat16*)out2;
                const int tstr = 3 * N;
                __nv_bfloat162 h0 = __float22bfloat162_rn(v0);
                __nv_bfloat162 h1 = __float22bfloat162_rn(v1);
                __nv_bfloat162 l0 = __float22bfloat162_rn(
                    make_float2(v0.x - __bfloat162float(h0.x), v0.y - __bfloat162float(h0.y)));
                __nv_bfloat162 l1 = __float22bfloat162_rn(
                    make_float2(v1.x - __bfloat162float(h1.x), v1.y - __bfloat162float(h1.y)));
                *reinterpret_cast<__nv_bfloat162*>(T + (long long)r * tstr + cl)          = h0;
                *reinterpret_cast<__nv_bfloat162*>(T + (long long)r * tstr + cl + N)      = l0;
                *reinterpret_cast<__nv_bfloat162*>(T + (long long)r * tstr + cl + 2 * N)  = h0;
                *reinterpret_cast<__nv_bfloat162*>(T + (long long)(r + 8) * tstr + cl)         = h1;
                *reinterpret_cast<__nv_bfloat162*>(T + (long long)(r + 8) * tstr + cl + N)     = l1;
                *reinterpret_cast<__nv_bfloat162*>(T + (long long)(r + 8) * tstr + cl + 2 * N) = h1;
            }
        }
    }
}

// ================= conversion kernels =================
__device__ __forceinline__ void hilo2(float2 v, __nv_bfloat162& h2, __nv_bfloat162& l2) {
    h2 = __float22bfloat162_rn(v);
    float2 r;
    r.x = v.x - __bfloat162float(h2.x);
    r.y = v.y - __bfloat162float(h2.y);
    l2 = __float22bfloat162_rn(r);
}

// in [R,K] f32 -> out [R,3K] bf16 (A-side: hi,hi,lo)
__global__ void split3_k(const float* __restrict__ in, __nv_bfloat16* __restrict__ out,
                         int K, long long total2)
{
    long long i = (long long)blockIdx.x * blockDim.x + threadIdx.x;
    if (i >= total2) return;
    long long e = i * 2;
    long long r = e / K;
    int c = (int)(e - r * K);
    float2 v = *reinterpret_cast<const float2*>(in + e);
    __nv_bfloat162 h2, l2;
    hilo2(v, h2, l2);
    __nv_bfloat16* o = out + r * (3LL * K);
    *reinterpret_cast<__nv_bfloat162*>(o + c)         = h2;
    *reinterpret_cast<__nv_bfloat162*>(o + c + K)     = h2;
    *reinterpret_cast<__nv_bfloat162*>(o + c + 2 * K) = l2;
}

// in [R,C] f32 -> out [C,3R] bf16 transposed (weights, B-side: hi,lo,hi)
__global__ void split3T_k(const float* __restrict__ in, __nv_bfloat16* __restrict__ out,
                          int R, int C)
{
    __shared__ float t[32][33];
    const int c0 = blockIdx.x * 32, r0 = blockIdx.y * 32;
    const int tx = threadIdx.x, ty = threadIdx.y;
#pragma unroll
    for (int i = 0; i < 4; i++)
        t[ty + i * 8][tx] = in[(long long)(r0 + ty + i * 8) * C + c0 + tx];
    __syncthreads();
#pragma unroll
    for (int i = 0; i < 4; i++) {
        int c = c0 + ty + i * 8;
        int r = r0 + tx;
        float x = t[tx][ty + i * 8];
        __nv_bfloat16 h = __float2bfloat16(x);
        __nv_bfloat16 l = __float2bfloat16(x - __bfloat162float(h));
        __nv_bfloat16* o = out + (long long)c * (3LL * R);
        o[r] = h;
        o[r + R]     = l;
        o[r + 2 * R] = h;
    }
}

// in [R,C] f32 -> out [C,R] fp16 transposed; batched
__global__ void cvtT_h(const float* __restrict__ in, __half* __restrict__ out,
                       int R, int C, long long inBS, long long outBS)
{
    __shared__ float t[32][33];
    const float* ib = in + inBS * blockIdx.z;
    __half* ob = out + outBS * blockIdx.z;
    const int c0 = blockIdx.x * 32, r0 = blockIdx.y * 32;
    const int tx = threadIdx.x, ty = threadIdx.y;
#pragma unroll
    for (int i = 0; i < 4; i++)
        t[ty + i * 8][tx] = ib[(long long)(r0 + ty + i * 8) * C + c0 + tx];
    __syncthreads();
#pragma unroll
    for (int i = 0; i < 4; i++) {
        int c = c0 + ty + i * 8;
        int r = r0 + tx;
        ob[(long long)c * R + r] = __float2half(t[tx][ty + i * 8]);
    }
}

// fp16 transpose: in [R,C] -> out [C,R]; batched; 64x64 tiles; block (32,8)
__global__ void cvtT_hh(const __half* __restrict__ in, __half* __restrict__ out,
                        int R, int C, long long inBS, long long outBS)
{
    __shared__ __half2 t[64][33];
    const __half* ib = in + inBS * blockIdx.z;
    __half* ob = out + outBS * blockIdx.z;
    const int c0 = blockIdx.x * 64, r0 = blockIdx.y * 64;
    const int tx = threadIdx.x, ty = threadIdx.y;
#pragma unroll
    for (int i = 0; i < 8; i++) {
        int row = ty + i * 8;
        t[row][tx] = reinterpret_cast<const __half2*>(ib + (long long)(r0 + row) * C + c0)[tx];
    }
    __syncthreads();
#pragma unroll
    for (int i = 0; i < 8; i++) {
        int cc = ty + i * 8;
        __half2 p0 = t[2 * tx][cc >> 1];
        __half2 p1 = t[2 * tx + 1][cc >> 1];
        __half x0 = (cc & 1) ? __high2half(p0) : __low2half(p0);
        __half x1 = (cc & 1) ? __high2half(p1) : __low2half(p1);
        reinterpret_cast<__half2*>(ob + (long long)(c0 + cc) * R + r0)[tx] =
            __halves2half2(x0, x1);
    }
}

// ================= softmax over 1024 columns -> fp16 ==========
__global__ __launch_bounds__(256)
void softmax1024(const float* __restrict__ W, __half* __restrict__ Wh)
{
    const long long row = blockIdx.x;
    const float* w = W + row * 1024;
    const int t = threadIdx.x;
    float4 v = reinterpret_cast<const float4*>(w)[t];
    float m = fmaxf(fmaxf(v.x, v.y), fmaxf(v.z, v.w));
#pragma unroll
    for (int o = 16; o > 0; o >>= 1) m = fmaxf(m, __shfl_xor_sync(0xffffffffu, m, o));
    __shared__ float smax[8], ssum[8];
    if ((t & 31) == 0) smax[t >> 5] = m;
    __syncthreads();
    float bmax = smax[0];
#pragma unroll
    for (int i = 1; i < 8; i++) bmax = fmaxf(bmax, smax[i]);
    v.x = __expf(v.x - bmax); v.y = __expf(v.y - bmax);
    v.z = __expf(v.z - bmax); v.w = __expf(v.w - bmax);
    float s = v.x + v.y + v.z + v.w;
#pragma unroll
    for (int o = 16; o > 0; o >>= 1) s += __shfl_xor_sync(0xffffffffu, s, o);
    if ((t & 31) == 0) ssum[t >> 5] = s;
    __syncthreads();
    float tot = 0.f;
#pragma unroll
    for (int i = 0; i < 8; i++) tot += ssum[i];
    const float inv = 1.f / tot;
    __half* wh = Wh + row * 1024 + t * 4;
    *reinterpret_cast<__half2*>(wh)     = __float22half2_rn(make_float2(v.x * inv, v.y * inv));
    *reinterpret_cast<__half2*>(wh + 2) = __float22half2_rn(make_float2(v.z * inv, v.w * inv));
}

// ================= launch =================
static inline int blk2(long long total2) { return (int)((total2 + 255) / 256); }

extern "C" void kernel_launch(void* const* d_in, const int* in_sizes, int n_in,
                              void* d_out, int out_size)
{
    (void)in_sizes; (void)n_in; (void)out_size;
    const float* A     = (const float*)d_in[0];
    const float* P     = (const float*)d_in[1];
    const float* G_w   = (const float*)d_in[2];
    const float* G_b   = (const float*)d_in[3];
    const float* fca_w = (const float*)d_in[4];
    const float* fca_b = (const float*)d_in[5];
    const float* fcp_w = (const float*)d_in[6];
    const float* fcp_b = (const float*)d_in[7];
    float* out = (float*)d_out;

    float *Ag, *W;
    cudaGetSymbolAddress((void**)&Ag, g_Ag);
    cudaGetSymbolAddress((void**)&W,  g_W);
    __nv_bfloat16 *A3, *P3, *Ag3, *Gt3;
    cudaGetSymbolAddress((void**)&A3,  g_A3);
    cudaGetSymbolAddress((void**)&P3,  g_P3);
    cudaGetSymbolAddress((void**)&Ag3, g_Ag3);
    cudaGetSymbolAddress((void**)&Gt3, g_Gt3);
    __half *Wh, *WTh, *AgTh, *PTh, *U6h, *U7h, *Fah, *Fph;
    cudaGetSymbolAddress((void**)&Wh,   g_Wh);
    cudaGetSymbolAddress((void**)&WTh,  g_WTh);
    cudaGetSymbolAddress((void**)&AgTh, g_AgTh);
    cudaGetSymbolAddress((void**)&PTh,  g_PTh);
    cudaGetSymbolAddress((void**)&U6h,  g_U6h);
    cudaGetSymbolAddress((void**)&U7h,  g_U7h);
    cudaGetSymbolAddress((void**)&Fah,  g_Fah);
    cudaGetSymbolAddress((void**)&Fph,  g_Fph);

    cudaFuncSetAttribute(tgemm<0,false>, cudaFuncAttributeMaxDynamicSharedMemorySize, SMEMSZ);
    cudaFuncSetAttribute(tgemm<4,false>, cudaFuncAttributeMaxDynamicSharedMemorySize, SMEMSZ);
    cudaFuncSetAttribute(tgemm<3,true>,  cudaFuncAttributeMaxDynamicSharedMemorySize, SMEMSZ);
    cudaFuncSetAttribute(tgemm<2,true>,  cudaFuncAttributeMaxDynamicSharedMemorySize, SMEMSZ);

    const dim3 tb(32, 8);

    // --- input conversions ---
    split3_k<<<blk2(16384LL*768/2), 256>>>(A, A3, 768, 16384LL*768/2);
    split3_k<<<blk2(32768LL*768/2), 256>>>(P, P3, 768, 32768LL*768/2);
    split3T_k<<<dim3(24, 24, 1), tb>>>(G_w, Gt3, 768, 768);
    cvtT_h<<<dim3(24, 48, 1),  tb>>>(fca_w, Fah, 1536, 768, 0, 0);
    cvtT_h<<<dim3(24, 48, 1),  tb>>>(fcp_w, Fph, 1536, 768, 0, 0);
    cvtT_h<<<dim3(24, 64, 16), tb>>>(P, PTh, 2048, 768, 2048LL*768, 768LL*2048);

    // 1) Ag = A @ G_w + G_b  (bf16 triple-K) -> fp32 Ag + bf16 triple Ag3
    tgemm<4,false><<<dim3(6, 128, 1), 128, SMEMSZ>>>(
        (const uint16_t*)A3, (const uint16_t*)Gt3, G_b, nullptr, Ag, Ag3,
        768, 2304, 0, 0, 0);

    cvtT_h<<<dim3(24, 32, 16), tb>>>(Ag, AgTh, 1024, 768, 1024LL*768, 768LL*1024);

    // 2) W = P @ Ag^T (per batch, bf16 triple-K) -> fp32 logits
    tgemm<0,false><<<dim3(8, 16, 16), 128, SMEMSZ>>>(
        (const uint16_t*)P3, (const uint16_t*)Ag3, nullptr, nullptr, W, nullptr,
        1024, 2304, 2048LL*2304, 1024LL*2304, 2048LL*1024);

    // 3) softmax over a-dim -> fp16 Wh only
    softmax1024<<<BSZ * PLEN, 256>>>(W, Wh);

    // fp16 transpose Wh -> WTh (per batch: [2048,1024] -> [1024,2048])
    cvtT_hh<<<dim3(16, 32, 16), tb>>>(Wh, WTh, 2048, 1024, 2048LL*1024, 1024LL*2048);

    // 4) MP = W @ Ag (per batch, fp16), fused combo with P -> U7h
    tgemm<3,true><<<dim3(6, 16, 16), 128, SMEMSZ>>>(
        (const uint16_t*)Wh, (const uint16_t*)AgTh, nullptr, P, nullptr, U7h,
        768, 1024, 2048LL*1024, 768LL*1024, 2048LL*768);

    // 5) MA = W^T @ P (per batch, fp16), fused combo with Ag -> U6h
    tgemm<3,true><<<dim3(6, 8, 16), 128, SMEMSZ>>>(
        (const uint16_t*)WTh, (const uint16_t*)PTh, nullptr, Ag, nullptr, U6h,
        768, 2048, 1024LL*2048, 768LL*2048, 1024LL*768);

    // 6) SA = relu(U6 @ fca_w + fca_b)
    tgemm<2,true><<<dim3(6, 128, 1), 128, SMEMSZ>>>(
        (const uint16_t*)U6h, (const uint16_t*)Fah, fca_b, nullptr, out, nullptr,
        768, 1536, 0, 0, 0);

    // 7) SP = relu(U7 @ fcp_w + fcp_b)
    tgemm<2,true><<<dim3(6, 256, 1), 128, SMEMSZ>>>(
        (const uint16_t*)U7h, (const uint16_t*)Fph, fcp_b, nullptr,
        out + 16384LL * 768, nullptr, 768, 1536, 0, 0, 0);
}